// round 2
// baseline (speedup 1.0000x reference)
#include <cuda_runtime.h>
#include <math.h>

#define BB 32
#define SS 400
#define TT 100
#define EE 256
#define HE 256
#define HD 512
#define VV 32000

// ---------------- scratch (device globals; no allocations) ----------------
__device__ float g_srcx[SS * BB * EE];          // (S,B,E)
__device__ float g_trgx[TT * BB * EE];          // (T,B,E)
__device__ float g_gif[SS * BB * 3 * HE];       // (S,B,768) x@Wih_f.T + bih_f
__device__ float g_gib[SS * BB * 3 * HE];       // (S,B,768) x@Wih_b.T + bih_b
__device__ float g_gidec[TT * BB * 3 * HD];     // (T,B,1536) emb part of dec gi + bih
__device__ float g_enhy[BB * SS * 2 * HE];      // (B,S,512)
__device__ float g_h[2][2][BB * HE];            // [dir][buf][b*HE+u]
__device__ float g_hcat[BB * 2 * HE];           // (B,512) [hT_f, hT_b]
__device__ float g_hdec[2][BB * HD];            // decoder hidden, double buffered
__device__ float g_ctx[BB * HD];                // (B,512)
__device__ float g_decout[BB * TT * HD];        // (B,T,512)

// ---------------- embedding gather ----------------
__global__ void embed_kernel(const int* __restrict__ ids, const float* __restrict__ table,
                             float* __restrict__ out, int seq) {
    int i = blockIdx.x * blockDim.x + threadIdx.x;
    int E4 = EE / 4;
    int total = seq * BB * E4;
    if (i >= total) return;
    int e4 = i % E4;
    int sb = i / E4;
    int b = sb % BB;
    int s = sb / BB;
    int id = ids[b * seq + s];
    ((float4*)out)[i] = ((const float4*)table)[(size_t)id * E4 + e4];
}

// ---------------- zero hidden-state init buffers ----------------
__global__ void zero_h_kernel() {
    int i = blockIdx.x * blockDim.x + threadIdx.x;
    if (i < 2 * BB * HE) {
        g_h[i / (BB * HE)][0][i % (BB * HE)] = 0.f;
    }
}

// ---------------- generic C = A(M,K) * B(N,K)^T + bias, row-major ----------------
// ldb: row stride of B (lets us slice dec_Wih's first 256 columns)
// act: 0 = none, 1 = tanh
__global__ void __launch_bounds__(256) gemm_atb(
    const float* __restrict__ A, const float* __restrict__ Bm,
    const float* __restrict__ bias, float* __restrict__ C,
    int M, int N, int K, int ldb, int act)
{
    __shared__ float sA[16][68];
    __shared__ float sB[16][68];
    int bm = blockIdx.y * 64, bn = blockIdx.x * 64;
    int tid = threadIdx.x;
    int tm = (tid >> 4) << 2, tn = (tid & 15) << 2;
    int lr = tid >> 2, lc = (tid & 3) << 2;
    float acc[4][4] = {};
    for (int k0 = 0; k0 < K; k0 += 16) {
        float4 a4 = make_float4(0.f, 0.f, 0.f, 0.f);
        if (bm + lr < M) a4 = *(const float4*)&A[(size_t)(bm + lr) * K + k0 + lc];
        sA[lc + 0][lr] = a4.x; sA[lc + 1][lr] = a4.y; sA[lc + 2][lr] = a4.z; sA[lc + 3][lr] = a4.w;
        float4 b4 = *(const float4*)&Bm[(size_t)(bn + lr) * ldb + k0 + lc];
        sB[lc + 0][lr] = b4.x; sB[lc + 1][lr] = b4.y; sB[lc + 2][lr] = b4.z; sB[lc + 3][lr] = b4.w;
        __syncthreads();
#pragma unroll
        for (int kk = 0; kk < 16; kk++) {
            float4 av = *(const float4*)&sA[kk][tm];
            float4 bv = *(const float4*)&sB[kk][tn];
            float a[4] = {av.x, av.y, av.z, av.w};
            float b[4] = {bv.x, bv.y, bv.z, bv.w};
#pragma unroll
            for (int i = 0; i < 4; i++)
#pragma unroll
                for (int j = 0; j < 4; j++) acc[i][j] += a[i] * b[j];
        }
        __syncthreads();
    }
#pragma unroll
    for (int i = 0; i < 4; i++) {
        int row = bm + tm + i;
        if (row >= M) continue;
        float4 v;
        float* pv = &v.x;
#pragma unroll
        for (int j = 0; j < 4; j++) {
            float x = acc[i][j] + bias[bn + tn + j];
            if (act == 1) x = tanhf(x);
            pv[j] = x;
        }
        *(float4*)&C[(size_t)row * N + bn + tn] = v;
    }
}

// ---------------- encoder recurrent step (both directions fused) ----------------
// grid: 128 CTAs (dir = bx>>6, 4 units each), 128 threads (b = tid&31, ul = tid>>5)
__global__ void __launch_bounds__(128) enc_step_kernel(
    const float* __restrict__ Whh_f, const float* __restrict__ Whh_b,
    const float* __restrict__ bhh_f, const float* __restrict__ bhh_b, int t)
{
    __shared__ float sh[HE * 33];   // h_prev [k][b] padded, 33.8 KB
    int dir = blockIdx.x >> 6;
    int ublk = blockIdx.x & 63;
    int tid = threadIdx.x;
    int b = tid & 31;
    int ul = tid >> 5;
    int u = ublk * 4 + ul;
    const float* hprev = g_h[dir][t & 1];
    float* hout = g_h[dir][(t + 1) & 1];
    for (int i = tid; i < BB * HE; i += 128) {
        int bb2 = i >> 8;
        int k = i & 255;
        sh[k * 33 + bb2] = hprev[i];
    }
    __syncthreads();
    const float* Whh = dir ? Whh_b : Whh_f;
    const float* bhh = dir ? bhh_b : bhh_f;
    const float4* wr = (const float4*)(Whh + (size_t)u * HE);
    const float4* wz = (const float4*)(Whh + (size_t)(HE + u) * HE);
    const float4* wn = (const float4*)(Whh + (size_t)(2 * HE + u) * HE);
    float ar = 0.f, az = 0.f, an = 0.f;
#pragma unroll 4
    for (int k4 = 0; k4 < HE / 4; k4++) {
        int k = k4 * 4;
        float h0 = sh[(k + 0) * 33 + b], h1 = sh[(k + 1) * 33 + b];
        float h2 = sh[(k + 2) * 33 + b], h3 = sh[(k + 3) * 33 + b];
        float4 w;
        w = wr[k4]; ar += h0 * w.x + h1 * w.y + h2 * w.z + h3 * w.w;
        w = wz[k4]; az += h0 * w.x + h1 * w.y + h2 * w.z + h3 * w.w;
        w = wn[k4]; an += h0 * w.x + h1 * w.y + h2 * w.z + h3 * w.w;
    }
    int s = dir ? (SS - 1 - t) : t;
    const float* gi = (dir ? g_gib : g_gif) + (size_t)(s * BB + b) * (3 * HE);
    float ghr = ar + bhh[u];
    float ghz = az + bhh[HE + u];
    float ghn = an + bhh[2 * HE + u];
    float r = 1.f / (1.f + expf(-(gi[u] + ghr)));
    float z = 1.f / (1.f + expf(-(gi[HE + u] + ghz)));
    float n = tanhf(gi[2 * HE + u] + r * ghn);
    float hp = sh[u * 33 + b];
    float hn2 = (1.f - z) * n + z * hp;
    hout[b * HE + u] = hn2;
    g_enhy[((size_t)b * SS + s) * (2 * HE) + dir * HE + u] = hn2;
}

// ---------------- build [hT_f, hT_b] ----------------
__global__ void hcat_kernel() {
    int i = blockIdx.x * blockDim.x + threadIdx.x;
    if (i >= BB * 2 * HE) return;
    int b = i >> 9;
    int j = i & 511;
    float v;
    if (j < HE) v = g_enhy[((size_t)b * SS + (SS - 1)) * (2 * HE) + j];
    else        v = g_enhy[((size_t)b * SS + 0) * (2 * HE) + j];
    g_hcat[i] = v;
}

// ---------------- decoder attention (scores + softmax + ctx), one CTA per batch ----------------
__global__ void __launch_bounds__(256) attn_step_kernel(int t) {
    __shared__ float shh[HD];
    __shared__ float sc[SS];
    __shared__ float red[256];
    int b = blockIdx.x;
    int tid = threadIdx.x;
    const float* hd = g_hdec[t & 1] + b * HD;
    for (int i = tid; i < HD; i += 256) shh[i] = hd[i];
    __syncthreads();
    int warp = tid >> 5, lane = tid & 31;
    const float* eb = g_enhy + (size_t)b * SS * (2 * HE);
    for (int s = warp; s < SS; s += 8) {
        const float4* e4 = (const float4*)(eb + (size_t)s * HD);
        float acc = 0.f;
        for (int k = lane; k < HD / 4; k += 32) {
            float4 e = e4[k];
            float4 h4 = *(const float4*)&shh[k * 4];
            acc += e.x * h4.x + e.y * h4.y + e.z * h4.z + e.w * h4.w;
        }
#pragma unroll
        for (int o = 16; o; o >>= 1) acc += __shfl_xor_sync(0xffffffffu, acc, o);
        if (lane == 0) sc[s] = acc;
    }
    __syncthreads();
    float m = -1e30f;
    for (int i = tid; i < SS; i += 256) m = fmaxf(m, sc[i]);
    red[tid] = m; __syncthreads();
    for (int st = 128; st > 0; st >>= 1) {
        if (tid < st) red[tid] = fmaxf(red[tid], red[tid + st]);
        __syncthreads();
    }
    float mx = red[0];
    __syncthreads();
    float sum = 0.f;
    for (int i = tid; i < SS; i += 256) { float e = expf(sc[i] - mx); sc[i] = e; sum += e; }
    red[tid] = sum; __syncthreads();
    for (int st = 128; st > 0; st >>= 1) {
        if (tid < st) red[tid] += red[tid + st];
        __syncthreads();
    }
    float inv = 1.f / red[0];
    __syncthreads();
    // ctx: 128 float4 outputs over 512 dims
    if (tid < 128) {
        float4 acc = make_float4(0.f, 0.f, 0.f, 0.f);
        const float4* e4 = (const float4*)eb;
        for (int s = 0; s < SS; s++) {
            float w = sc[s] * inv;
            float4 e = e4[(size_t)s * (HD / 4) + tid];
            acc.x += w * e.x; acc.y += w * e.y; acc.z += w * e.z; acc.w += w * e.w;
        }
        float4 o;
        o.x = tanhf(acc.x); o.y = tanhf(acc.y); o.z = tanhf(acc.z); o.w = tanhf(acc.w);
        ((float4*)(g_ctx + b * HD))[tid] = o;
    }
}

// ---------------- decoder GRU step ----------------
// grid: 128 CTAs (4 units each), 128 threads (b = tid&31, ul = tid>>5)
__global__ void __launch_bounds__(128) dec_step_kernel(
    const float* __restrict__ dWih, const float* __restrict__ dWhh,
    const float* __restrict__ dbhh, int t)
{
    extern __shared__ float sm[];
    float* shh = sm;              // h_prev [k][b] padded (512*33)
    float* shc = sm + HD * 33;    // ctx    [k][b] padded (512*33)
    int tid = threadIdx.x;
    int b = tid & 31;
    int ul = tid >> 5;
    int u = blockIdx.x * 4 + ul;
    const float* hprev = g_hdec[t & 1];
    for (int i = tid; i < BB * HD; i += 128) {
        int bb2 = i >> 9;
        int k = i & 511;
        shh[k * 33 + bb2] = hprev[i];
        shc[k * 33 + bb2] = g_ctx[i];
    }
    __syncthreads();
    const float4* wr = (const float4*)(dWhh + (size_t)u * HD);
    const float4* wz = (const float4*)(dWhh + (size_t)(HD + u) * HD);
    const float4* wn = (const float4*)(dWhh + (size_t)(2 * HD + u) * HD);
    const float4* vr = (const float4*)(dWih + (size_t)u * 768 + 256);
    const float4* vz = (const float4*)(dWih + (size_t)(HD + u) * 768 + 256);
    const float4* vn = (const float4*)(dWih + (size_t)(2 * HD + u) * 768 + 256);
    float ar = 0.f, az = 0.f, an = 0.f, cr = 0.f, cz = 0.f, cn = 0.f;
#pragma unroll 2
    for (int k4 = 0; k4 < HD / 4; k4++) {
        int k = k4 * 4;
        float h0 = shh[(k + 0) * 33 + b], h1 = shh[(k + 1) * 33 + b];
        float h2 = shh[(k + 2) * 33 + b], h3 = shh[(k + 3) * 33 + b];
        float c0 = shc[(k + 0) * 33 + b], c1 = shc[(k + 1) * 33 + b];
        float c2 = shc[(k + 2) * 33 + b], c3 = shc[(k + 3) * 33 + b];
        float4 w;
        w = wr[k4]; ar += h0 * w.x + h1 * w.y + h2 * w.z + h3 * w.w;
        w = wz[k4]; az += h0 * w.x + h1 * w.y + h2 * w.z + h3 * w.w;
        w = wn[k4]; an += h0 * w.x + h1 * w.y + h2 * w.z + h3 * w.w;
        w = vr[k4]; cr += c0 * w.x + c1 * w.y + c2 * w.z + c3 * w.w;
        w = vz[k4]; cz += c0 * w.x + c1 * w.y + c2 * w.z + c3 * w.w;
        w = vn[k4]; cn += c0 * w.x + c1 * w.y + c2 * w.z + c3 * w.w;
    }
    const float* gi = g_gidec + ((size_t)t * BB + b) * (3 * HD);
    float ghr = ar + dbhh[u];
    float ghz = az + dbhh[HD + u];
    float ghn = an + dbhh[2 * HD + u];
    float r = 1.f / (1.f + expf(-(gi[u] + cr + ghr)));
    float z = 1.f / (1.f + expf(-(gi[HD + u] + cz + ghz)));
    float n = tanhf(gi[2 * HD + u] + cn + r * ghn);
    float hp = shh[u * 33 + b];
    float hn2 = (1.f - z) * n + z * hp;
    g_hdec[(t + 1) & 1][b * HD + u] = hn2;
    g_decout[((size_t)b * TT + t) * HD + u] = hn2;
}

// ---------------- host ----------------
extern "C" void kernel_launch(void* const* d_in, const int* in_sizes, int n_in,
                              void* d_out, int out_size) {
    const int*   src_ids = (const int*)d_in[0];
    const int*   trg_ids = (const int*)d_in[1];
    const float* src_emb = (const float*)d_in[2];
    const float* trg_emb = (const float*)d_in[3];
    const float* eWihf   = (const float*)d_in[4];
    const float* eWhhf   = (const float*)d_in[5];
    const float* ebihf   = (const float*)d_in[6];
    const float* ebhhf   = (const float*)d_in[7];
    const float* eWihb   = (const float*)d_in[8];
    const float* eWhhb   = (const float*)d_in[9];
    const float* ebihb   = (const float*)d_in[10];
    const float* ebhhb   = (const float*)d_in[11];
    const float* e2dW    = (const float*)d_in[12];
    const float* e2db    = (const float*)d_in[13];
    const float* dWih    = (const float*)d_in[14];
    const float* dWhh    = (const float*)d_in[15];
    const float* dbih    = (const float*)d_in[16];
    const float* dbhh    = (const float*)d_in[17];
    const float* outW    = (const float*)d_in[18];
    const float* outb    = (const float*)d_in[19];
    float* out = (float*)d_out;

    cudaFuncSetAttribute(dec_step_kernel, cudaFuncAttributeMaxDynamicSharedMemorySize,
                         2 * HD * 33 * (int)sizeof(float));

    float *p_srcx, *p_trgx, *p_gif, *p_gib, *p_gidec, *p_hcat, *p_hdec, *p_decout;
    cudaGetSymbolAddress((void**)&p_srcx, g_srcx);
    cudaGetSymbolAddress((void**)&p_trgx, g_trgx);
    cudaGetSymbolAddress((void**)&p_gif, g_gif);
    cudaGetSymbolAddress((void**)&p_gib, g_gib);
    cudaGetSymbolAddress((void**)&p_gidec, g_gidec);
    cudaGetSymbolAddress((void**)&p_hcat, g_hcat);
    cudaGetSymbolAddress((void**)&p_hdec, g_hdec);
    cudaGetSymbolAddress((void**)&p_decout, g_decout);

    // 1) embeddings
    embed_kernel<<<(SS * BB * (EE / 4) + 255) / 256, 256>>>(src_ids, src_emb, p_srcx, SS);
    embed_kernel<<<(TT * BB * (EE / 4) + 255) / 256, 256>>>(trg_ids, trg_emb, p_trgx, TT);

    // 2) time-parallel input-side GRU GEMMs
    dim3 g1(768 / 64, (SS * BB) / 64);
    gemm_atb<<<g1, 256>>>(p_srcx, eWihf, ebihf, p_gif, SS * BB, 768, 256, 256, 0);
    gemm_atb<<<g1, 256>>>(p_srcx, eWihb, ebihb, p_gib, SS * BB, 768, 256, 256, 0);
    dim3 g2(1536 / 64, (TT * BB) / 64);
    gemm_atb<<<g2, 256>>>(p_trgx, dWih, dbih, p_gidec, TT * BB, 1536, 256, 768, 0);

    // 3) encoder recurrent scan (both dirs fused per step)
    zero_h_kernel<<<(2 * BB * HE + 255) / 256, 256>>>();
    for (int t = 0; t < SS; t++)
        enc_step_kernel<<<128, 128>>>(eWhhf, eWhhb, ebhhf, ebhhb, t);

    // 4) h0 = tanh([hT_f,hT_b] @ e2d_W.T + e2d_b)
    hcat_kernel<<<(BB * 2 * HE + 255) / 256, 256>>>();
    dim3 g3(512 / 64, 1);
    gemm_atb<<<g3, 256>>>(p_hcat, e2dW, e2db, p_hdec, BB, 512, 512, 512, 1);

    // 5) decoder scan
    for (int t = 0; t < TT; t++) {
        attn_step_kernel<<<BB, 256>>>(t);
        dec_step_kernel<<<128, 128, 2 * HD * 33 * sizeof(float)>>>(dWih, dWhh, dbhh, t);
    }

    // 6) logits = dec_out @ out_W.T + out_b   (written directly to d_out)
    dim3 g4(VV / 64, (BB * TT) / 64);
    gemm_atb<<<g4, 256>>>(p_decout, outW, outb, out, BB * TT, VV, 512, 512, 0);
}

// round 3
// speedup vs baseline: 1.4745x; 1.4745x over previous
#include <cuda_runtime.h>
#include <math.h>

#define BB 32
#define SS 400
#define TT 100
#define EE 256
#define HE 256
#define HD 512
#define VV 32000

// ---------------- scratch (device globals; no allocations) ----------------
__device__ float g_srcx[SS * BB * EE];
__device__ float g_trgx[TT * BB * EE];
__device__ float g_gif[SS * BB * 3 * HE];
__device__ float g_gib[SS * BB * 3 * HE];
__device__ float g_gidec[TT * BB * 3 * HD];
__device__ float g_enhy[BB * SS * 2 * HE];      // (B,S,512) read-only in decoder
__device__ float g_h[2][2][BB * HE];            // [dir][parity][b*HE+u]
__device__ float g_hcat[BB * 2 * HE];
__device__ float g_hdec[2][BB * HD];
__device__ float g_ctx[BB * HD];
__device__ float g_decout[BB * TT * HD];
// attention partials: [chunk][b]
__device__ float g_attm[4][BB];
__device__ float g_attl[4][BB];
__device__ float g_attc[4][BB][HD];
// grid barrier state
__device__ unsigned g_bar_cnt[8];
__device__ unsigned g_bar_gen[8];

// ---------------- software grid barrier (all CTAs resident) ----------------
__device__ __forceinline__ void grid_bar(int slot, unsigned target, unsigned ncta) {
    __syncthreads();
    if (threadIdx.x == 0) {
        __threadfence();
        unsigned prev = atomicAdd(&g_bar_cnt[slot], 1u);
        if (prev == ncta - 1u) {
            g_bar_cnt[slot] = 0u;
            __threadfence();
            atomicExch(&g_bar_gen[slot], target);
        } else {
            while (((volatile unsigned*)g_bar_gen)[slot] < target) __nanosleep(64);
        }
    }
    __syncthreads();
}

// ---------------- embedding gather ----------------
__global__ void embed_kernel(const int* __restrict__ ids, const float* __restrict__ table,
                             float* __restrict__ out, int seq) {
    int i = blockIdx.x * blockDim.x + threadIdx.x;
    int E4 = EE / 4;
    int total = seq * BB * E4;
    if (i >= total) return;
    int e4 = i % E4;
    int sb = i / E4;
    int b = sb % BB;
    int s = sb / BB;
    int id = ids[b * seq + s];
    ((float4*)out)[i] = ((const float4*)table)[(size_t)id * E4 + e4];
}

// ---------------- prep: zero h0 + barrier state ----------------
__global__ void prep_kernel() {
    int i = blockIdx.x * blockDim.x + threadIdx.x;
    if (i < 8) { g_bar_cnt[i] = 0u; g_bar_gen[i] = 0u; }
    if (i < 2 * BB * HE) {
        g_h[i / (BB * HE)][0][i % (BB * HE)] = 0.f;
    }
}

// ---------------- small generic GEMM (used for e2d only, M=32) ----------------
__global__ void __launch_bounds__(256) gemm_atb(
    const float* __restrict__ A, const float* __restrict__ Bm,
    const float* __restrict__ bias, float* __restrict__ C,
    int M, int N, int K, int ldb, int act)
{
    __shared__ float sA[16][68];
    __shared__ float sB[16][68];
    int bm = blockIdx.y * 64, bn = blockIdx.x * 64;
    int tid = threadIdx.x;
    int tm = (tid >> 4) << 2, tn = (tid & 15) << 2;
    int lr = tid >> 2, lc = (tid & 3) << 2;
    float acc[4][4] = {};
    for (int k0 = 0; k0 < K; k0 += 16) {
        float4 a4 = make_float4(0.f, 0.f, 0.f, 0.f);
        if (bm + lr < M) a4 = *(const float4*)&A[(size_t)(bm + lr) * K + k0 + lc];
        sA[lc + 0][lr] = a4.x; sA[lc + 1][lr] = a4.y; sA[lc + 2][lr] = a4.z; sA[lc + 3][lr] = a4.w;
        float4 b4 = *(const float4*)&Bm[(size_t)(bn + lr) * ldb + k0 + lc];
        sB[lc + 0][lr] = b4.x; sB[lc + 1][lr] = b4.y; sB[lc + 2][lr] = b4.z; sB[lc + 3][lr] = b4.w;
        __syncthreads();
#pragma unroll
        for (int kk = 0; kk < 16; kk++) {
            float4 av = *(const float4*)&sA[kk][tm];
            float4 bv = *(const float4*)&sB[kk][tn];
            float a[4] = {av.x, av.y, av.z, av.w};
            float b[4] = {bv.x, bv.y, bv.z, bv.w};
#pragma unroll
            for (int i = 0; i < 4; i++)
#pragma unroll
                for (int j = 0; j < 4; j++) acc[i][j] += a[i] * b[j];
        }
        __syncthreads();
    }
#pragma unroll
    for (int i = 0; i < 4; i++) {
        int row = bm + tm + i;
        if (row >= M) continue;
        float4 v;
        float* pv = &v.x;
#pragma unroll
        for (int j = 0; j < 4; j++) {
            float x = acc[i][j] + bias[bn + tn + j];
            if (act == 1) x = tanhf(x);
            pv[j] = x;
        }
        *(float4*)&C[(size_t)row * N + bn + tn] = v;
    }
}

// ---------------- big GEMM: 128x64 tile, 8x4/thread, reg prefetch ----------------
// C(M,N) = A(M,K) * B(N,K)^T + bias. Requires M%128==0, N%64==0, K%16==0.
__global__ void __launch_bounds__(256) gemm_big(
    const float* __restrict__ A, const float* __restrict__ Bm,
    const float* __restrict__ bias, float* __restrict__ C,
    int M, int N, int K, int ldb, int act)
{
    __shared__ float sA[16][132];
    __shared__ float sB[16][68];
    int bm = blockIdx.y * 128, bn = blockIdx.x * 64;
    int tid = threadIdx.x;
    int tm = (tid >> 4) << 3, tn = (tid & 15) << 2;
    int lr = tid >> 2, lc = (tid & 3) << 2;
    const float* Ap0 = A + (size_t)(bm + lr) * K + lc;
    const float* Ap1 = Ap0 + (size_t)64 * K;
    const float* Bp  = Bm + (size_t)(bn + lr) * ldb + lc;
    float4 pa0 = *(const float4*)Ap0;
    float4 pa1 = *(const float4*)Ap1;
    float4 pb  = *(const float4*)Bp;
    float acc[8][4] = {};
    for (int k0 = 0; k0 < K; k0 += 16) {
        sA[lc + 0][lr] = pa0.x; sA[lc + 1][lr] = pa0.y; sA[lc + 2][lr] = pa0.z; sA[lc + 3][lr] = pa0.w;
        sA[lc + 0][lr + 64] = pa1.x; sA[lc + 1][lr + 64] = pa1.y; sA[lc + 2][lr + 64] = pa1.z; sA[lc + 3][lr + 64] = pa1.w;
        sB[lc + 0][lr] = pb.x; sB[lc + 1][lr] = pb.y; sB[lc + 2][lr] = pb.z; sB[lc + 3][lr] = pb.w;
        __syncthreads();
        if (k0 + 16 < K) {
            pa0 = *(const float4*)(Ap0 + k0 + 16);
            pa1 = *(const float4*)(Ap1 + k0 + 16);
            pb  = *(const float4*)(Bp  + k0 + 16);
        }
#pragma unroll
        for (int kk = 0; kk < 16; kk++) {
            float4 a0 = *(const float4*)&sA[kk][tm];
            float4 a1 = *(const float4*)&sA[kk][tm + 4];
            float4 b  = *(const float4*)&sB[kk][tn];
            float av[8] = {a0.x, a0.y, a0.z, a0.w, a1.x, a1.y, a1.z, a1.w};
            float bv[4] = {b.x, b.y, b.z, b.w};
#pragma unroll
            for (int i = 0; i < 8; i++)
#pragma unroll
                for (int j = 0; j < 4; j++) acc[i][j] += av[i] * bv[j];
        }
        __syncthreads();
    }
#pragma unroll
    for (int i = 0; i < 8; i++) {
        int row = bm + tm + i;
        float4 v;
        float* pv = &v.x;
#pragma unroll
        for (int j = 0; j < 4; j++) {
            float x = acc[i][j] + bias[bn + tn + j];
            if (act == 1) x = tanhf(x);
            pv[j] = x;
        }
        *(float4*)&C[(size_t)row * N + bn + tn] = v;
    }
}

// ---------------- persistent encoder: 64 CTAs, 400 steps, per-dir barrier ----------------
// CTA c: dir=c>>5, ublk=c&31 (8 units). 128 thr: b=tid&31, ul=tid>>5 -> units u0,u0+4.
__global__ void __launch_bounds__(128) enc_persist(
    const float* __restrict__ Whh_f, const float* __restrict__ Whh_b,
    const float* __restrict__ bhh_f, const float* __restrict__ bhh_b)
{
    __shared__ float sh[HE * 33];
    int c = blockIdx.x;
    int dir = c >> 5;
    int ublk = c & 31;
    int tid = threadIdx.x;
    int b = tid & 31;
    int ul = tid >> 5;
    int u0 = ublk * 8 + ul;
    int u1 = u0 + 4;
    const float* Whh = dir ? Whh_b : Whh_f;
    const float* bhh = dir ? bhh_b : bhh_f;
    const float* gibase = dir ? g_gib : g_gif;
    const float4* w0r = (const float4*)(Whh + (size_t)u0 * HE);
    const float4* w0z = (const float4*)(Whh + (size_t)(HE + u0) * HE);
    const float4* w0n = (const float4*)(Whh + (size_t)(2 * HE + u0) * HE);
    const float4* w1r = (const float4*)(Whh + (size_t)u1 * HE);
    const float4* w1z = (const float4*)(Whh + (size_t)(HE + u1) * HE);
    const float4* w1n = (const float4*)(Whh + (size_t)(2 * HE + u1) * HE);
    float b0r = bhh[u0], b0z = bhh[HE + u0], b0n = bhh[2 * HE + u0];
    float b1r = bhh[u1], b1z = bhh[HE + u1], b1n = bhh[2 * HE + u1];

    for (int t = 0; t < SS; t++) {
        const float* hprev = g_h[dir][t & 1];
        float* hout = g_h[dir][(t + 1) & 1];
        for (int i = tid; i < BB * HE; i += 128)
            sh[(i & 255) * 33 + (i >> 8)] = __ldcg(&hprev[i]);
        __syncthreads();
        float a0r = 0.f, a0z = 0.f, a0n = 0.f, a1r = 0.f, a1z = 0.f, a1n = 0.f;
#pragma unroll 4
        for (int k4 = 0; k4 < HE / 4; k4++) {
            int k = k4 * 4;
            float h0 = sh[(k + 0) * 33 + b], h1 = sh[(k + 1) * 33 + b];
            float h2 = sh[(k + 2) * 33 + b], h3 = sh[(k + 3) * 33 + b];
            float4 w;
            w = __ldg(&w0r[k4]); a0r += h0 * w.x + h1 * w.y + h2 * w.z + h3 * w.w;
            w = __ldg(&w0z[k4]); a0z += h0 * w.x + h1 * w.y + h2 * w.z + h3 * w.w;
            w = __ldg(&w0n[k4]); a0n += h0 * w.x + h1 * w.y + h2 * w.z + h3 * w.w;
            w = __ldg(&w1r[k4]); a1r += h0 * w.x + h1 * w.y + h2 * w.z + h3 * w.w;
            w = __ldg(&w1z[k4]); a1z += h0 * w.x + h1 * w.y + h2 * w.z + h3 * w.w;
            w = __ldg(&w1n[k4]); a1n += h0 * w.x + h1 * w.y + h2 * w.z + h3 * w.w;
        }
        int s = dir ? (SS - 1 - t) : t;
        const float* gi = gibase + (size_t)(s * BB + b) * (3 * HE);
        {
            float ghr = a0r + b0r, ghz = a0z + b0z, ghn = a0n + b0n;
            float r = 1.f / (1.f + expf(-(__ldg(&gi[u0]) + ghr)));
            float z = 1.f / (1.f + expf(-(__ldg(&gi[HE + u0]) + ghz)));
            float n = tanhf(__ldg(&gi[2 * HE + u0]) + r * ghn);
            float hp = sh[u0 * 33 + b];
            float hn2 = (1.f - z) * n + z * hp;
            hout[b * HE + u0] = hn2;
            g_enhy[((size_t)b * SS + s) * (2 * HE) + dir * HE + u0] = hn2;
        }
        {
            float ghr = a1r + b1r, ghz = a1z + b1z, ghn = a1n + b1n;
            float r = 1.f / (1.f + expf(-(__ldg(&gi[u1]) + ghr)));
            float z = 1.f / (1.f + expf(-(__ldg(&gi[HE + u1]) + ghz)));
            float n = tanhf(__ldg(&gi[2 * HE + u1]) + r * ghn);
            float hp = sh[u1 * 33 + b];
            float hn2 = (1.f - z) * n + z * hp;
            hout[b * HE + u1] = hn2;
            g_enhy[((size_t)b * SS + s) * (2 * HE) + dir * HE + u1] = hn2;
        }
        grid_bar(dir, (unsigned)(t + 1), 32u);
    }
}

// ---------------- build [hT_f, hT_b] ----------------
__global__ void hcat_kernel() {
    int i = blockIdx.x * blockDim.x + threadIdx.x;
    if (i >= BB * 2 * HE) return;
    int b = i >> 9;
    int j = i & 511;
    float v;
    if (j < HE) v = g_enhy[((size_t)b * SS + (SS - 1)) * (2 * HE) + j];
    else        v = g_enhy[((size_t)b * SS + 0) * (2 * HE) + j];
    g_hcat[i] = v;
}

// ---------------- persistent decoder: 128 CTAs x 256 thr, 100 steps ----------------
// Phase A: flash attention partials. CTA c: b=c&31, chunk=c>>5 (100 s each).
// Phase R: CTAs 0..31 combine 4 partials -> g_ctx (tanh applied).
// Phase G: GRU. thread: b=tid&31, slot=(tid>>5)&3 -> unit u=c*4+slot, which=tid>>7
//          (which==0: h-dots via dWhh; which==1: ctx-dots via dWih[:,256:]).
__global__ void __launch_bounds__(256) dec_persist(
    const float* __restrict__ dWih, const float* __restrict__ dWhh,
    const float* __restrict__ dbhh)
{
    extern __shared__ float sm[];
    // phase G layout:
    float* shh = sm;                  // [512][33]
    float* shc = sm + HD * 33;        // [512][33]
    float* smx = sm + 2 * HD * 33;    // [3][132]
    // phase A layout (reuses front of sm):
    float* sm_m  = sm;                // [8]
    float* sm_l  = sm + 8;            // [8]
    float* sm_ctx = sm + 16;          // [8][512]

    int c = blockIdx.x;
    int tid = threadIdx.x;
    int lane = tid & 31;
    int w = tid >> 5;

    int ab = c & 31;          // phase A batch
    int chunk = c >> 5;       // phase A s-chunk
    int s0 = chunk * (SS / 4);

    int gb = tid & 31;            // phase G batch
    int slot = (tid >> 5) & 3;    // phase G unit slot
    int which = tid >> 7;         // 0: h-dots, 1: ctx-dots
    int gu = c * 4 + slot;        // phase G unit (0..511)

    const float4* gwr;
    const float4* gwz;
    const float4* gwn;
    if (which == 0) {
        gwr = (const float4*)(dWhh + (size_t)gu * HD);
        gwz = (const float4*)(dWhh + (size_t)(HD + gu) * HD);
        gwn = (const float4*)(dWhh + (size_t)(2 * HD + gu) * HD);
    } else {
        gwr = (const float4*)(dWih + (size_t)gu * 768 + 256);
        gwz = (const float4*)(dWih + (size_t)(HD + gu) * 768 + 256);
        gwn = (const float4*)(dWih + (size_t)(2 * HD + gu) * 768 + 256);
    }

    for (int t = 0; t < TT; t++) {
        const float* hcur = g_hdec[t & 1];
        // ---------- Phase A: flash attention partial ----------
        {
            const float* hd = hcur + ab * HD;
            float4 hreg[4];
#pragma unroll
            for (int j = 0; j < 4; j++)
                hreg[j] = __ldcg((const float4*)(hd + (j * 32 + lane) * 4));
            const float* eb = g_enhy + (size_t)ab * SS * HD;
            float m = -1e30f, l = 0.f;
            float4 cacc[4];
#pragma unroll
            for (int j = 0; j < 4; j++) cacc[j] = make_float4(0.f, 0.f, 0.f, 0.f);
            for (int s = s0 + w; s < s0 + SS / 4; s += 8) {
                const float4* e4 = (const float4*)(eb + (size_t)s * HD);
                float4 ev[4];
                float acc = 0.f;
#pragma unroll
                for (int j = 0; j < 4; j++) {
                    ev[j] = __ldg(&e4[j * 32 + lane]);
                    acc += ev[j].x * hreg[j].x + ev[j].y * hreg[j].y
                         + ev[j].z * hreg[j].z + ev[j].w * hreg[j].w;
                }
#pragma unroll
                for (int o = 16; o; o >>= 1) acc += __shfl_xor_sync(0xffffffffu, acc, o);
                float mnew = fmaxf(m, acc);
                float scale = __expf(m - mnew);
                float p = __expf(acc - mnew);
                l = l * scale + p;
#pragma unroll
                for (int j = 0; j < 4; j++) {
                    cacc[j].x = cacc[j].x * scale + p * ev[j].x;
                    cacc[j].y = cacc[j].y * scale + p * ev[j].y;
                    cacc[j].z = cacc[j].z * scale + p * ev[j].z;
                    cacc[j].w = cacc[j].w * scale + p * ev[j].w;
                }
                m = mnew;
            }
            if (lane == 0) { sm_m[w] = m; sm_l[w] = l; }
#pragma unroll
            for (int j = 0; j < 4; j++)
                ((float4*)(sm_ctx + w * HD))[j * 32 + lane] = cacc[j];
            __syncthreads();
            float M = -1e30f;
#pragma unroll
            for (int q = 0; q < 8; q++) M = fmaxf(M, sm_m[q]);
            float f[8];
            float L = 0.f;
#pragma unroll
            for (int q = 0; q < 8; q++) { f[q] = __expf(sm_m[q] - M); L += sm_l[q] * f[q]; }
            for (int e = tid; e < HD; e += 256) {
                float v = 0.f;
#pragma unroll
                for (int q = 0; q < 8; q++) v += sm_ctx[q * HD + e] * f[q];
                g_attc[chunk][ab][e] = v;
            }
            if (tid == 0) { g_attm[chunk][ab] = M; g_attl[chunk][ab] = L; }
        }
        grid_bar(2, (unsigned)(3 * t + 1), 128u);
        // ---------- Phase R: combine partials -> ctx ----------
        if (c < 32) {
            int b = c;
            float m0 = __ldcg(&g_attm[0][b]), m1 = __ldcg(&g_attm[1][b]);
            float m2 = __ldcg(&g_attm[2][b]), m3 = __ldcg(&g_attm[3][b]);
            float M = fmaxf(fmaxf(m0, m1), fmaxf(m2, m3));
            float f0 = __expf(m0 - M), f1 = __expf(m1 - M);
            float f2 = __expf(m2 - M), f3 = __expf(m3 - M);
            float L = __ldcg(&g_attl[0][b]) * f0 + __ldcg(&g_attl[1][b]) * f1
                    + __ldcg(&g_attl[2][b]) * f2 + __ldcg(&g_attl[3][b]) * f3;
            float inv = 1.f / L;
            for (int e = tid; e < HD; e += 256) {
                float v = __ldcg(&g_attc[0][b][e]) * f0 + __ldcg(&g_attc[1][b][e]) * f1
                        + __ldcg(&g_attc[2][b][e]) * f2 + __ldcg(&g_attc[3][b][e]) * f3;
                g_ctx[b * HD + e] = tanhf(v * inv);
            }
        }
        grid_bar(2, (unsigned)(3 * t + 2), 128u);
        // ---------- Phase G: GRU step ----------
        {
            for (int i = tid; i < BB * HD; i += 256) {
                int b2 = i >> 9;
                int k = i & 511;
                shh[k * 33 + b2] = __ldcg(&hcur[i]);
                shc[k * 33 + b2] = __ldcg(&g_ctx[i]);
            }
            __syncthreads();
            const float* src = (which == 0) ? shh : shc;
            float ar = 0.f, az = 0.f, an = 0.f;
#pragma unroll 2
            for (int k4 = 0; k4 < HD / 4; k4++) {
                int k = k4 * 4;
                float h0 = src[(k + 0) * 33 + gb], h1 = src[(k + 1) * 33 + gb];
                float h2 = src[(k + 2) * 33 + gb], h3 = src[(k + 3) * 33 + gb];
                float4 ww;
                ww = __ldg(&gwr[k4]); ar += h0 * ww.x + h1 * ww.y + h2 * ww.z + h3 * ww.w;
                ww = __ldg(&gwz[k4]); az += h0 * ww.x + h1 * ww.y + h2 * ww.z + h3 * ww.w;
                ww = __ldg(&gwn[k4]); an += h0 * ww.x + h1 * ww.y + h2 * ww.z + h3 * ww.w;
            }
            int p = tid & 127;
            if (which == 1) {
                smx[0 * 132 + p] = ar;
                smx[1 * 132 + p] = az;
                smx[2 * 132 + p] = an;
            }
            __syncthreads();
            if (which == 0) {
                float cr = smx[0 * 132 + p], cz = smx[1 * 132 + p], cn = smx[2 * 132 + p];
                const float* gi = g_gidec + ((size_t)t * BB + gb) * (3 * HD);
                float ghr = ar + __ldg(&dbhh[gu]);
                float ghz = az + __ldg(&dbhh[HD + gu]);
                float ghn = an + __ldg(&dbhh[2 * HD + gu]);
                float r = 1.f / (1.f + expf(-(__ldg(&gi[gu]) + cr + ghr)));
                float z = 1.f / (1.f + expf(-(__ldg(&gi[HD + gu]) + cz + ghz)));
                float n = tanhf(__ldg(&gi[2 * HD + gu]) + cn + r * ghn);
                float hp = shh[gu * 33 + gb];
                float hn2 = (1.f - z) * n + z * hp;
                g_hdec[(t + 1) & 1][gb * HD + gu] = hn2;
                g_decout[((size_t)gb * TT + t) * HD + gu] = hn2;
            }
        }
        grid_bar(2, (unsigned)(3 * t + 3), 128u);
    }
}

// ---------------- host ----------------
extern "C" void kernel_launch(void* const* d_in, const int* in_sizes, int n_in,
                              void* d_out, int out_size) {
    const int*   src_ids = (const int*)d_in[0];
    const int*   trg_ids = (const int*)d_in[1];
    const float* src_emb = (const float*)d_in[2];
    const float* trg_emb = (const float*)d_in[3];
    const float* eWihf   = (const float*)d_in[4];
    const float* eWhhf   = (const float*)d_in[5];
    const float* ebihf   = (const float*)d_in[6];
    const float* ebhhf   = (const float*)d_in[7];
    const float* eWihb   = (const float*)d_in[8];
    const float* eWhhb   = (const float*)d_in[9];
    const float* ebihb   = (const float*)d_in[10];
    const float* ebhhb   = (const float*)d_in[11];
    const float* e2dW    = (const float*)d_in[12];
    const float* e2db    = (const float*)d_in[13];
    const float* dWih    = (const float*)d_in[14];
    const float* dWhh    = (const float*)d_in[15];
    const float* dbih    = (const float*)d_in[16];
    const float* dbhh    = (const float*)d_in[17];
    const float* outW    = (const float*)d_in[18];
    const float* outb    = (const float*)d_in[19];
    float* out = (float*)d_out;

    const int DEC_SMEM = (2 * HD * 33 + 3 * 132) * (int)sizeof(float);
    cudaFuncSetAttribute(dec_persist, cudaFuncAttributeMaxDynamicSharedMemorySize, DEC_SMEM);

    float *p_srcx, *p_trgx, *p_gif, *p_gib, *p_gidec, *p_hcat, *p_hdec, *p_decout;
    cudaGetSymbolAddress((void**)&p_srcx, g_srcx);
    cudaGetSymbolAddress((void**)&p_trgx, g_trgx);
    cudaGetSymbolAddress((void**)&p_gif, g_gif);
    cudaGetSymbolAddress((void**)&p_gib, g_gib);
    cudaGetSymbolAddress((void**)&p_gidec, g_gidec);
    cudaGetSymbolAddress((void**)&p_hcat, g_hcat);
    cudaGetSymbolAddress((void**)&p_hdec, g_hdec);
    cudaGetSymbolAddress((void**)&p_decout, g_decout);

    // 1) embeddings + prep
    embed_kernel<<<(SS * BB * (EE / 4) + 255) / 256, 256>>>(src_ids, src_emb, p_srcx, SS);
    embed_kernel<<<(TT * BB * (EE / 4) + 255) / 256, 256>>>(trg_ids, trg_emb, p_trgx, TT);
    prep_kernel<<<(2 * BB * HE + 255) / 256, 256>>>();

    // 2) time-parallel input-side GRU GEMMs (M%128==0, N%64==0)
    dim3 g1(768 / 64, (SS * BB) / 128);
    gemm_big<<<g1, 256>>>(p_srcx, eWihf, ebihf, p_gif, SS * BB, 768, 256, 256, 0);
    gemm_big<<<g1, 256>>>(p_srcx, eWihb, ebihb, p_gib, SS * BB, 768, 256, 256, 0);
    dim3 g2(1536 / 64, (TT * BB) / 128);
    gemm_big<<<g2, 256>>>(p_trgx, dWih, dbih, p_gidec, TT * BB, 1536, 256, 768, 0);

    // 3) persistent encoder scan (1 launch, 400 steps)
    enc_persist<<<64, 128>>>(eWhhf, eWhhb, ebhhf, ebhhb);

    // 4) h0 = tanh([hT_f,hT_b] @ e2d_W.T + e2d_b)
    hcat_kernel<<<(BB * 2 * HE + 255) / 256, 256>>>();
    dim3 g3(512 / 64, 1);
    gemm_atb<<<g3, 256>>>(p_hcat, e2dW, e2db, p_hdec, BB, 512, 512, 512, 1);

    // 5) persistent decoder scan (1 launch, 100 steps)
    dec_persist<<<128, 256, DEC_SMEM>>>(dWih, dWhh, dbhh);

    // 6) logits = dec_out @ out_W.T + out_b
    dim3 g4(VV / 64, (BB * TT) / 128);
    gemm_big<<<g4, 256>>>(p_decout, outW, outb, out, BB * TT, VV, 512, 512, 0);
}

// round 4
// speedup vs baseline: 2.3976x; 1.6260x over previous
#include <cuda_runtime.h>
#include <math.h>

#define BB 32
#define SS 400
#define TT 100
#define EE 256
#define HE 256
#define HD 512
#define VV 32000

// ---------------- scratch (device globals; no allocations) ----------------
__device__ float g_srcx[SS * BB * EE];
__device__ float g_trgx[TT * BB * EE];
__device__ float g_gif[SS * BB * 3 * HE];
__device__ float g_gib[SS * BB * 3 * HE];
__device__ float g_gidec[TT * BB * 3 * HD];
__device__ float g_enhy[BB * SS * 2 * HE];
__device__ float g_h[2][2][BB * HE];
__device__ float g_hcat[BB * 2 * HE];
__device__ float g_hdec[2][BB * HD];
__device__ float g_ctx[BB * HD];
__device__ float g_decout[BB * TT * HD];
__device__ float g_attm[4][BB];
__device__ float g_attl[4][BB];
__device__ float g_attc[4][BB][HD];
__device__ unsigned g_bar_cnt[8];
__device__ unsigned g_bar_gen[8];

// ---------------- software grid barrier ----------------
__device__ __forceinline__ void grid_bar(int slot, unsigned target, unsigned ncta) {
    __syncthreads();
    if (threadIdx.x == 0) {
        __threadfence();
        unsigned prev = atomicAdd(&g_bar_cnt[slot], 1u);
        if (prev == ncta - 1u) {
            g_bar_cnt[slot] = 0u;
            __threadfence();
            atomicExch(&g_bar_gen[slot], target);
        } else {
            while (((volatile unsigned*)g_bar_gen)[slot] < target) __nanosleep(32);
        }
    }
    __syncthreads();
}

// ---------------- embedding gather ----------------
__global__ void embed_kernel(const int* __restrict__ ids, const float* __restrict__ table,
                             float* __restrict__ out, int seq) {
    int i = blockIdx.x * blockDim.x + threadIdx.x;
    int E4 = EE / 4;
    int total = seq * BB * E4;
    if (i >= total) return;
    int e4 = i % E4;
    int sb = i / E4;
    int b = sb % BB;
    int s = sb / BB;
    int id = ids[b * seq + s];
    ((float4*)out)[i] = ((const float4*)table)[(size_t)id * E4 + e4];
}

// ---------------- prep ----------------
__global__ void prep_kernel() {
    int i = blockIdx.x * blockDim.x + threadIdx.x;
    if (i < 8) { g_bar_cnt[i] = 0u; g_bar_gen[i] = 0u; }
    if (i < 2 * BB * HE) g_h[i / (BB * HE)][0][i % (BB * HE)] = 0.f;
}

// ---------------- tf32 -> bits ----------------
__device__ __forceinline__ unsigned f2t(float x) {
    unsigned r; asm("cvt.rna.tf32.f32 %0, %1;" : "=r"(r) : "f"(x)); return r;
}

// ---------------- tf32 tensor-core GEMM: C = A(M,K)*B(N,K)^T + bias ----------------
// 128x64 tile, 256 thr (8 warps: wm=w&3 rows, wn=w>>2 cols). M%128==0, N%64==0, K%16==0.
__global__ void __launch_bounds__(256) gemm_tf32(
    const float* __restrict__ A, const float* __restrict__ Bm,
    const float* __restrict__ bias, float* __restrict__ C,
    int M, int N, int K, int ldb)
{
    __shared__ unsigned sA[16][132];
    __shared__ unsigned sB[16][68];
    int bm = blockIdx.y * 128, bn = blockIdx.x * 64;
    int tid = threadIdx.x;
    int w = tid >> 5, lane = tid & 31;
    int wm = w & 3, wn = w >> 2;
    int g = lane >> 2, tg = lane & 3;
    int arow = tid >> 1, acol = (tid & 1) * 8;
    int brow = tid >> 2, bcol = (tid & 3) * 4;
    const float* Ap = A + (size_t)(bm + arow) * K + acol;
    const float* Bp = Bm + (size_t)(bn + brow) * ldb + bcol;
    float4 pa0 = *(const float4*)Ap;
    float4 pa1 = *(const float4*)(Ap + 4);
    float4 pb  = *(const float4*)Bp;
    float d[2][4][4];
#pragma unroll
    for (int f = 0; f < 2; f++)
#pragma unroll
        for (int j = 0; j < 4; j++)
#pragma unroll
            for (int e = 0; e < 4; e++) d[f][j][e] = 0.f;

    for (int k0 = 0; k0 < K; k0 += 16) {
        sA[acol + 0][arow] = f2t(pa0.x); sA[acol + 1][arow] = f2t(pa0.y);
        sA[acol + 2][arow] = f2t(pa0.z); sA[acol + 3][arow] = f2t(pa0.w);
        sA[acol + 4][arow] = f2t(pa1.x); sA[acol + 5][arow] = f2t(pa1.y);
        sA[acol + 6][arow] = f2t(pa1.z); sA[acol + 7][arow] = f2t(pa1.w);
        sB[bcol + 0][brow] = f2t(pb.x);  sB[bcol + 1][brow] = f2t(pb.y);
        sB[bcol + 2][brow] = f2t(pb.z);  sB[bcol + 3][brow] = f2t(pb.w);
        __syncthreads();
        if (k0 + 16 < K) {
            pa0 = *(const float4*)(Ap + k0 + 16);
            pa1 = *(const float4*)(Ap + k0 + 20);
            pb  = *(const float4*)(Bp + k0 + 16);
        }
#pragma unroll
        for (int kk = 0; kk < 16; kk += 8) {
            unsigned a[2][4], bf[4][2];
#pragma unroll
            for (int f = 0; f < 2; f++) {
                int mr = wm * 32 + f * 16 + g;
                a[f][0] = sA[kk + tg][mr];
                a[f][1] = sA[kk + tg][mr + 8];
                a[f][2] = sA[kk + tg + 4][mr];
                a[f][3] = sA[kk + tg + 4][mr + 8];
            }
#pragma unroll
            for (int j = 0; j < 4; j++) {
                int nc = wn * 32 + j * 8 + g;
                bf[j][0] = sB[kk + tg][nc];
                bf[j][1] = sB[kk + tg + 4][nc];
            }
#pragma unroll
            for (int f = 0; f < 2; f++)
#pragma unroll
                for (int j = 0; j < 4; j++)
                    asm volatile(
                        "mma.sync.aligned.m16n8k8.row.col.f32.tf32.tf32.f32 "
                        "{%0,%1,%2,%3}, {%4,%5,%6,%7}, {%8,%9}, {%0,%1,%2,%3};"
                        : "+f"(d[f][j][0]), "+f"(d[f][j][1]),
                          "+f"(d[f][j][2]), "+f"(d[f][j][3])
                        : "r"(a[f][0]), "r"(a[f][1]), "r"(a[f][2]), "r"(a[f][3]),
                          "r"(bf[j][0]), "r"(bf[j][1]));
        }
        __syncthreads();
    }
#pragma unroll
    for (int f = 0; f < 2; f++) {
        int r0 = bm + wm * 32 + f * 16 + g;
#pragma unroll
        for (int j = 0; j < 4; j++) {
            int col = bn + wn * 32 + j * 8 + tg * 2;
            float b0 = __ldg(&bias[col]), b1 = __ldg(&bias[col + 1]);
            float2 v0 = make_float2(d[f][j][0] + b0, d[f][j][1] + b1);
            float2 v1 = make_float2(d[f][j][2] + b0, d[f][j][3] + b1);
            *(float2*)&C[(size_t)r0 * N + col] = v0;
            *(float2*)&C[(size_t)(r0 + 8) * N + col] = v1;
        }
    }
}

// ---------------- small fp32 GEMM (e2d only, M=32, tanh) ----------------
__global__ void __launch_bounds__(256) gemm_atb(
    const float* __restrict__ A, const float* __restrict__ Bm,
    const float* __restrict__ bias, float* __restrict__ C,
    int M, int N, int K, int ldb, int act)
{
    __shared__ float sA[16][68];
    __shared__ float sB[16][68];
    int bm = blockIdx.y * 64, bn = blockIdx.x * 64;
    int tid = threadIdx.x;
    int tm = (tid >> 4) << 2, tn = (tid & 15) << 2;
    int lr = tid >> 2, lc = (tid & 3) << 2;
    float acc[4][4] = {};
    for (int k0 = 0; k0 < K; k0 += 16) {
        float4 a4 = make_float4(0.f, 0.f, 0.f, 0.f);
        if (bm + lr < M) a4 = *(const float4*)&A[(size_t)(bm + lr) * K + k0 + lc];
        sA[lc + 0][lr] = a4.x; sA[lc + 1][lr] = a4.y; sA[lc + 2][lr] = a4.z; sA[lc + 3][lr] = a4.w;
        float4 b4 = *(const float4*)&Bm[(size_t)(bn + lr) * ldb + k0 + lc];
        sB[lc + 0][lr] = b4.x; sB[lc + 1][lr] = b4.y; sB[lc + 2][lr] = b4.z; sB[lc + 3][lr] = b4.w;
        __syncthreads();
#pragma unroll
        for (int kk = 0; kk < 16; kk++) {
            float4 av = *(const float4*)&sA[kk][tm];
            float4 bv = *(const float4*)&sB[kk][tn];
            float a[4] = {av.x, av.y, av.z, av.w};
            float b[4] = {bv.x, bv.y, bv.z, bv.w};
#pragma unroll
            for (int i = 0; i < 4; i++)
#pragma unroll
                for (int j = 0; j < 4; j++) acc[i][j] += a[i] * b[j];
        }
        __syncthreads();
    }
#pragma unroll
    for (int i = 0; i < 4; i++) {
        int row = bm + tm + i;
        if (row >= M) continue;
        float4 v;
        float* pv = &v.x;
#pragma unroll
        for (int j = 0; j < 4; j++) {
            float x = acc[i][j] + bias[bn + tn + j];
            if (act == 1) x = tanhf(x);
            pv[j] = x;
        }
        *(float4*)&C[(size_t)row * N + bn + tn] = v;
    }
}

// ---------------- persistent encoder: 64 CTAs x 256 thr, weights in smem ----------------
__global__ void __launch_bounds__(256) enc_persist(
    const float* __restrict__ Whh_f, const float* __restrict__ Whh_b,
    const float* __restrict__ bhh_f, const float* __restrict__ bhh_b)
{
    extern __shared__ float es[];
    float* swt = es;            // [3*8*256] weights for this CTA's 8 units
    float* sh  = es + 6144;     // [256*33] h transposed
    int c = blockIdx.x;
    int dir = c >> 5;
    int ublk = c & 31;
    int tid = threadIdx.x;
    int b = tid & 31;
    int ul = tid >> 5;
    int u = ublk * 8 + ul;
    const float* Whh = dir ? Whh_b : Whh_f;
    const float* bhh = dir ? bhh_b : bhh_f;
    const float* gibase = dir ? g_gib : g_gif;
    for (int i = tid; i < 6144; i += 256) {
        int gate = i >> 11;
        int rem = i & 2047;
        swt[i] = Whh[((size_t)gate * HE + ublk * 8 + (rem >> 8)) * HE + (rem & 255)];
    }
    float br_ = bhh[u], bz_ = bhh[HE + u], bn_ = bhh[2 * HE + u];
    const float4* wr = (const float4*)&swt[(0 * 8 + ul) * 256];
    const float4* wz = (const float4*)&swt[(1 * 8 + ul) * 256];
    const float4* wn = (const float4*)&swt[(2 * 8 + ul) * 256];
    __syncthreads();

    for (int t = 0; t < SS; t++) {
        const float* hprev = g_h[dir][t & 1];
        float* hout = g_h[dir][(t + 1) & 1];
        for (int i = tid; i < BB * HE; i += 256)
            sh[(i & 255) * 33 + (i >> 8)] = __ldcg(&hprev[i]);
        __syncthreads();
        float ar = 0.f, az = 0.f, an = 0.f;
#pragma unroll 8
        for (int k4 = 0; k4 < 64; k4++) {
            int k = k4 * 4;
            float h0 = sh[(k + 0) * 33 + b], h1 = sh[(k + 1) * 33 + b];
            float h2 = sh[(k + 2) * 33 + b], h3 = sh[(k + 3) * 33 + b];
            float4 ww;
            ww = wr[k4]; ar += h0 * ww.x + h1 * ww.y + h2 * ww.z + h3 * ww.w;
            ww = wz[k4]; az += h0 * ww.x + h1 * ww.y + h2 * ww.z + h3 * ww.w;
            ww = wn[k4]; an += h0 * ww.x + h1 * ww.y + h2 * ww.z + h3 * ww.w;
        }
        int s = dir ? (SS - 1 - t) : t;
        const float* gi = gibase + (size_t)(s * BB + b) * (3 * HE);
        float ghr = ar + br_, ghz = az + bz_, ghn = an + bn_;
        float r = 1.f / (1.f + expf(-(__ldg(&gi[u]) + ghr)));
        float z = 1.f / (1.f + expf(-(__ldg(&gi[HE + u]) + ghz)));
        float n = tanhf(__ldg(&gi[2 * HE + u]) + r * ghn);
        float hp = sh[u * 33 + b];
        float hn2 = (1.f - z) * n + z * hp;
        hout[b * HE + u] = hn2;
        g_enhy[((size_t)b * SS + s) * (2 * HE) + dir * HE + u] = hn2;
        grid_bar(dir, (unsigned)(t + 1), 32u);
    }
}

// ---------------- build [hT_f, hT_b] ----------------
__global__ void hcat_kernel() {
    int i = blockIdx.x * blockDim.x + threadIdx.x;
    if (i >= BB * 2 * HE) return;
    int b = i >> 9;
    int j = i & 511;
    float v;
    if (j < HE) v = g_enhy[((size_t)b * SS + (SS - 1)) * (2 * HE) + j];
    else        v = g_enhy[((size_t)b * SS + 0) * (2 * HE) + j];
    g_hcat[i] = v;
}

// ---------------- persistent decoder: 128 CTAs x 512 thr ----------------
// Phase A: flash attention partials (16 warps, CTA c: b=c&31, chunk=c>>5).
// Phase R: distributed combine -> g_ctx (tanh).
// Phase G: GRU, 4-way split: which = tid>>7: (src = which>>1 [h|ctx], khalf = which&1).
__global__ void __launch_bounds__(512) dec_persist(
    const float* __restrict__ dWih, const float* __restrict__ dWhh,
    const float* __restrict__ dbhh)
{
    extern __shared__ float sm[];
    float* swd = sm;                    // [12288] weights (4 units x 3 gates x (h512|ctx512))
    float* shh = sm + 12288;            // [512*33]
    float* shc = shh + 16896;           // [512*33]
    float* smx = shc + 16896;           // [9*132]
    // phase A overlay (after swd):
    float* sm_m   = sm + 12288;         // [16]
    float* sm_l   = sm_m + 16;          // [16]
    float* sm_ctx = sm_l + 16;          // [16*512]

    int c = blockIdx.x;
    int tid = threadIdx.x;
    int lane = tid & 31, w = tid >> 5;
    int ab = c & 31, chunk = c >> 5, s0 = chunk * (SS / 4);
    int gb = tid & 31;
    int slot = (tid >> 5) & 3;
    int which = tid >> 7;               // 0..3
    int gu = c * 4 + slot;

    for (int i = tid; i < 12288; i += 512) {
        int sg = i >> 11;               // (s*3+g) 0..5
        int rem = i & 2047;
        int sl = rem >> 9;
        int k = rem & 511;
        int s_ = sg / 3, g2 = sg % 3;
        int uu = c * 4 + sl;
        swd[i] = (s_ == 0) ? dWhh[((size_t)g2 * HD + uu) * HD + k]
                           : dWih[((size_t)(g2 * HD + uu)) * 768 + 256 + k];
    }
    int ws = which >> 1;
    int kb = (which & 1) * 256;
    const float4* vr = (const float4*)&swd[((ws * 3 + 0) * 4 + slot) * 512 + kb];
    const float4* vz = (const float4*)&swd[((ws * 3 + 1) * 4 + slot) * 512 + kb];
    const float4* vn = (const float4*)&swd[((ws * 3 + 2) * 4 + slot) * 512 + kb];
    float db_r = dbhh[gu], db_z = dbhh[HD + gu], db_n = dbhh[2 * HD + gu];
    __syncthreads();

    for (int t = 0; t < TT; t++) {
        const float* hcur = g_hdec[t & 1];
        // ---------- Phase A ----------
        {
            const float* hd = hcur + ab * HD;
            float4 hreg[4];
#pragma unroll
            for (int j = 0; j < 4; j++)
                hreg[j] = __ldcg((const float4*)(hd + (j * 32 + lane) * 4));
            const float* eb = g_enhy + (size_t)ab * SS * HD;
            float m = -1e30f, l = 0.f;
            float4 cacc[4];
#pragma unroll
            for (int j = 0; j < 4; j++) cacc[j] = make_float4(0.f, 0.f, 0.f, 0.f);
            for (int s = s0 + w; s < s0 + SS / 4; s += 16) {
                const float4* e4 = (const float4*)(eb + (size_t)s * HD);
                float4 ev[4];
                float acc = 0.f;
#pragma unroll
                for (int j = 0; j < 4; j++) {
                    ev[j] = __ldg(&e4[j * 32 + lane]);
                    acc += ev[j].x * hreg[j].x + ev[j].y * hreg[j].y
                         + ev[j].z * hreg[j].z + ev[j].w * hreg[j].w;
                }
#pragma unroll
                for (int o = 16; o; o >>= 1) acc += __shfl_xor_sync(0xffffffffu, acc, o);
                float mnew = fmaxf(m, acc);
                float scale = __expf(m - mnew);
                float p = __expf(acc - mnew);
                l = l * scale + p;
#pragma unroll
                for (int j = 0; j < 4; j++) {
                    cacc[j].x = cacc[j].x * scale + p * ev[j].x;
                    cacc[j].y = cacc[j].y * scale + p * ev[j].y;
                    cacc[j].z = cacc[j].z * scale + p * ev[j].z;
                    cacc[j].w = cacc[j].w * scale + p * ev[j].w;
                }
                m = mnew;
            }
            if (lane == 0) { sm_m[w] = m; sm_l[w] = l; }
#pragma unroll
            for (int j = 0; j < 4; j++)
                ((float4*)(sm_ctx + w * HD))[j * 32 + lane] = cacc[j];
            __syncthreads();
            float M = -1e30f;
#pragma unroll
            for (int q = 0; q < 16; q++) M = fmaxf(M, sm_m[q]);
            float L = 0.f, vv = 0.f;
            int e = tid;  // 512 threads, HD=512
#pragma unroll
            for (int q = 0; q < 16; q++) {
                float f_ = __expf(sm_m[q] - M);
                L += sm_l[q] * f_;
                vv += sm_ctx[q * HD + e] * f_;
            }
            g_attc[chunk][ab][e] = vv;
            if (tid == 0) { g_attm[chunk][ab] = M; g_attl[chunk][ab] = L; }
        }
        grid_bar(2, (unsigned)(3 * t + 1), 128u);
        // ---------- Phase R: distributed combine ----------
        if (tid < 128) {
            int idx = c * 128 + tid;
            int b2 = idx >> 9, e = idx & 511;
            float m0 = __ldcg(&g_attm[0][b2]), m1 = __ldcg(&g_attm[1][b2]);
            float m2 = __ldcg(&g_attm[2][b2]), m3 = __ldcg(&g_attm[3][b2]);
            float M = fmaxf(fmaxf(m0, m1), fmaxf(m2, m3));
            float f0 = __expf(m0 - M), f1 = __expf(m1 - M);
            float f2 = __expf(m2 - M), f3 = __expf(m3 - M);
            float L = __ldcg(&g_attl[0][b2]) * f0 + __ldcg(&g_attl[1][b2]) * f1
                    + __ldcg(&g_attl[2][b2]) * f2 + __ldcg(&g_attl[3][b2]) * f3;
            float v = __ldcg(&g_attc[0][b2][e]) * f0 + __ldcg(&g_attc[1][b2][e]) * f1
                    + __ldcg(&g_attc[2][b2][e]) * f2 + __ldcg(&g_attc[3][b2][e]) * f3;
            g_ctx[b2 * HD + e] = tanhf(v / L);
        }
        grid_bar(2, (unsigned)(3 * t + 2), 128u);
        // ---------- Phase G ----------
        {
            for (int i = tid; i < BB * HD; i += 512) {
                int b2 = i >> 9, k = i & 511;
                shh[k * 33 + b2] = __ldcg(&hcur[i]);
                shc[k * 33 + b2] = __ldcg(&g_ctx[i]);
            }
            __syncthreads();
            const float* src = ws ? shc : shh;
            float ar = 0.f, az = 0.f, an = 0.f;
#pragma unroll 8
            for (int k4 = 0; k4 < 64; k4++) {
                int k = kb + k4 * 4;
                float h0 = src[(k + 0) * 33 + gb], h1 = src[(k + 1) * 33 + gb];
                float h2 = src[(k + 2) * 33 + gb], h3 = src[(k + 3) * 33 + gb];
                float4 ww;
                ww = vr[k4]; ar += h0 * ww.x + h1 * ww.y + h2 * ww.z + h3 * ww.w;
                ww = vz[k4]; az += h0 * ww.x + h1 * ww.y + h2 * ww.z + h3 * ww.w;
                ww = vn[k4]; an += h0 * ww.x + h1 * ww.y + h2 * ww.z + h3 * ww.w;
            }
            int p = tid & 127;
            if (which != 0) {
                smx[((which - 1) * 3 + 0) * 132 + p] = ar;
                smx[((which - 1) * 3 + 1) * 132 + p] = az;
                smx[((which - 1) * 3 + 2) * 132 + p] = an;
            }
            __syncthreads();
            if (which == 0) {
                float ar2 = ar + smx[0 * 132 + p];
                float az2 = az + smx[1 * 132 + p];
                float an2 = an + smx[2 * 132 + p];
                float cr = smx[3 * 132 + p] + smx[6 * 132 + p];
                float cz = smx[4 * 132 + p] + smx[7 * 132 + p];
                float cn = smx[5 * 132 + p] + smx[8 * 132 + p];
                const float* gi = g_gidec + ((size_t)t * BB + gb) * (3 * HD);
                float ghr = ar2 + db_r, ghz = az2 + db_z, ghn = an2 + db_n;
                float r = 1.f / (1.f + expf(-(__ldg(&gi[gu]) + cr + ghr)));
                float z = 1.f / (1.f + expf(-(__ldg(&gi[HD + gu]) + cz + ghz)));
                float n = tanhf(__ldg(&gi[2 * HD + gu]) + cn + r * ghn);
                float hp = shh[gu * 33 + gb];
                float hn2 = (1.f - z) * n + z * hp;
                g_hdec[(t + 1) & 1][gb * HD + gu] = hn2;
                g_decout[((size_t)gb * TT + t) * HD + gu] = hn2;
            }
        }
        grid_bar(2, (unsigned)(3 * t + 3), 128u);
    }
}

// ---------------- host ----------------
extern "C" void kernel_launch(void* const* d_in, const int* in_sizes, int n_in,
                              void* d_out, int out_size) {
    const int*   src_ids = (const int*)d_in[0];
    const int*   trg_ids = (const int*)d_in[1];
    const float* src_emb = (const float*)d_in[2];
    const float* trg_emb = (const float*)d_in[3];
    const float* eWihf   = (const float*)d_in[4];
    const float* eWhhf   = (const float*)d_in[5];
    const float* ebihf   = (const float*)d_in[6];
    const float* ebhhf   = (const float*)d_in[7];
    const float* eWihb   = (const float*)d_in[8];
    const float* eWhhb   = (const float*)d_in[9];
    const float* ebihb   = (const float*)d_in[10];
    const float* ebhhb   = (const float*)d_in[11];
    const float* e2dW    = (const float*)d_in[12];
    const float* e2db    = (const float*)d_in[13];
    const float* dWih    = (const float*)d_in[14];
    const float* dWhh    = (const float*)d_in[15];
    const float* dbih    = (const float*)d_in[16];
    const float* dbhh    = (const float*)d_in[17];
    const float* outW    = (const float*)d_in[18];
    const float* outb    = (const float*)d_in[19];
    float* out = (float*)d_out;

    const int ENC_SMEM = (6144 + HE * 33) * (int)sizeof(float);                    // 58368
    const int DEC_SMEM = (12288 + 2 * HD * 33 + 9 * 132) * (int)sizeof(float);     // 189072
    cudaFuncSetAttribute(enc_persist, cudaFuncAttributeMaxDynamicSharedMemorySize, ENC_SMEM);
    cudaFuncSetAttribute(dec_persist, cudaFuncAttributeMaxDynamicSharedMemorySize, DEC_SMEM);

    float *p_srcx, *p_trgx, *p_gif, *p_gib, *p_gidec, *p_hcat, *p_hdec, *p_decout;
    cudaGetSymbolAddress((void**)&p_srcx, g_srcx);
    cudaGetSymbolAddress((void**)&p_trgx, g_trgx);
    cudaGetSymbolAddress((void**)&p_gif, g_gif);
    cudaGetSymbolAddress((void**)&p_gib, g_gib);
    cudaGetSymbolAddress((void**)&p_gidec, g_gidec);
    cudaGetSymbolAddress((void**)&p_hcat, g_hcat);
    cudaGetSymbolAddress((void**)&p_hdec, g_hdec);
    cudaGetSymbolAddress((void**)&p_decout, g_decout);

    // 1) embeddings + prep
    embed_kernel<<<(SS * BB * (EE / 4) + 255) / 256, 256>>>(src_ids, src_emb, p_srcx, SS);
    embed_kernel<<<(TT * BB * (EE / 4) + 255) / 256, 256>>>(trg_ids, trg_emb, p_trgx, TT);
    prep_kernel<<<(2 * BB * HE + 255) / 256, 256>>>();

    // 2) time-parallel input-side GRU GEMMs (tf32 tensor cores)
    gemm_tf32<<<dim3(768 / 64, SS * BB / 128), 256>>>(p_srcx, eWihf, ebihf, p_gif, SS * BB, 768, 256, 256);
    gemm_tf32<<<dim3(768 / 64, SS * BB / 128), 256>>>(p_srcx, eWihb, ebihb, p_gib, SS * BB, 768, 256, 256);
    gemm_tf32<<<dim3(1536 / 64, TT * BB / 128), 256>>>(p_trgx, dWih, dbih, p_gidec, TT * BB, 1536, 256, 768);

    // 3) persistent encoder scan
    enc_persist<<<64, 256, ENC_SMEM>>>(eWhhf, eWhhb, ebhhf, ebhhb);

    // 4) h0 = tanh([hT_f,hT_b] @ e2d_W.T + e2d_b)
    hcat_kernel<<<(BB * 2 * HE + 255) / 256, 256>>>();
    gemm_atb<<<dim3(512 / 64, 1), 256>>>(p_hcat, e2dW, e2db, p_hdec, BB, 512, 512, 512, 1);

    // 5) persistent decoder scan
    dec_persist<<<128, 512, DEC_SMEM>>>(dWih, dWhh, dbhh);

    // 6) logits = dec_out @ out_W.T + out_b (tf32 tensor cores)
    gemm_tf32<<<dim3(VV / 64, BB * TT / 128), 256>>>(p_decout, outW, outb, out, BB * TT, VV, 512, 512);
}

// round 5
// speedup vs baseline: 2.5017x; 1.0434x over previous
#include <cuda_runtime.h>
#include <math.h>

#define BB 32
#define SS 400
#define TT 100
#define EE 256
#define HE 256
#define HD 512
#define VV 32000

// ---------------- scratch (device globals; no allocations) ----------------
__device__ float g_srcx[SS * BB * EE];
__device__ float g_trgx[TT * BB * EE];
__device__ float g_gif[SS * BB * 3 * HE];
__device__ float g_gib[SS * BB * 3 * HE];
__device__ float g_gidec[TT * BB * 3 * HD];
__device__ float g_enhy[BB * SS * 2 * HE];
__device__ float g_h[2][2][BB * HE];
__device__ float g_hcat[BB * 2 * HE];
__device__ float g_hdec[2][BB * HD];
__device__ float g_ctx[BB * HD];
__device__ float g_decout[BB * TT * HD];
__device__ float g_attm[4][BB];
__device__ float g_attl[4][BB];
__device__ float g_attc[4][BB][HD];
__device__ unsigned g_bar_cnt[8];
__device__ unsigned g_bar_gen[8];

// ---------------- software grid barrier ----------------
__device__ __forceinline__ void grid_bar(int slot, unsigned target, unsigned ncta) {
    __syncthreads();
    if (threadIdx.x == 0) {
        __threadfence();
        unsigned prev = atomicAdd(&g_bar_cnt[slot], 1u);
        if (prev == ncta - 1u) {
            g_bar_cnt[slot] = 0u;
            __threadfence();
            atomicExch(&g_bar_gen[slot], target);
        } else {
            while (((volatile unsigned*)g_bar_gen)[slot] < target) __nanosleep(32);
        }
    }
    __syncthreads();
}

// ---------------- embedding gather ----------------
__global__ void embed_kernel(const int* __restrict__ ids, const float* __restrict__ table,
                             float* __restrict__ out, int seq) {
    int i = blockIdx.x * blockDim.x + threadIdx.x;
    int E4 = EE / 4;
    int total = seq * BB * E4;
    if (i >= total) return;
    int e4 = i % E4;
    int sb = i / E4;
    int b = sb % BB;
    int s = sb / BB;
    int id = ids[b * seq + s];
    ((float4*)out)[i] = ((const float4*)table)[(size_t)id * E4 + e4];
}

// ---------------- prep ----------------
__global__ void prep_kernel() {
    int i = blockIdx.x * blockDim.x + threadIdx.x;
    if (i < 8) { g_bar_cnt[i] = 0u; g_bar_gen[i] = 0u; }
    if (i < 2 * BB * HE) g_h[i / (BB * HE)][0][i % (BB * HE)] = 0.f;
}

// ---------------- tf32 -> bits ----------------
__device__ __forceinline__ unsigned f2t(float x) {
    unsigned r; asm("cvt.rna.tf32.f32 %0, %1;" : "=r"(r) : "f"(x)); return r;
}

// ---------------- tf32 tensor-core GEMM v2: C = A(M,K)*B(N,K)^T + bias ----------------
// 128x64 tile, 256 thr, 8 warps (wm=w&3, wn=w>>2), warp tile 32x32.
// Double-buffered smem, conflict-free padded strides, one sync per k16.
__global__ void __launch_bounds__(256) gemm_tf32(
    const float* __restrict__ A, const float* __restrict__ Bm,
    const float* __restrict__ bias, float* __restrict__ C,
    int M, int N, int K, int ldb)
{
    __shared__ unsigned sA[2][16][136];
    __shared__ unsigned sB[2][16][72];
    int bm = blockIdx.y * 128, bn = blockIdx.x * 64;
    int tid = threadIdx.x;
    int w = tid >> 5, lane = tid & 31;
    int wm = w & 3, wn = w >> 2;
    int g = lane >> 2, tg = lane & 3;
    int arow = tid >> 1, acol = (tid & 1) * 8;
    int brow = tid >> 2, bcol = (tid & 3) * 4;
    const float* Ap = A + (size_t)(bm + arow) * K + acol;
    const float* Bp = Bm + (size_t)(bn + brow) * ldb + bcol;

    float4 pa0 = *(const float4*)Ap;
    float4 pa1 = *(const float4*)(Ap + 4);
    float4 pb  = *(const float4*)Bp;
    // stage 0 fill
    sA[0][acol + 0][arow] = f2t(pa0.x); sA[0][acol + 1][arow] = f2t(pa0.y);
    sA[0][acol + 2][arow] = f2t(pa0.z); sA[0][acol + 3][arow] = f2t(pa0.w);
    sA[0][acol + 4][arow] = f2t(pa1.x); sA[0][acol + 5][arow] = f2t(pa1.y);
    sA[0][acol + 6][arow] = f2t(pa1.z); sA[0][acol + 7][arow] = f2t(pa1.w);
    sB[0][bcol + 0][brow] = f2t(pb.x);  sB[0][bcol + 1][brow] = f2t(pb.y);
    sB[0][bcol + 2][brow] = f2t(pb.z);  sB[0][bcol + 3][brow] = f2t(pb.w);
    __syncthreads();

    float d[2][4][4];
#pragma unroll
    for (int f = 0; f < 2; f++)
#pragma unroll
        for (int j = 0; j < 4; j++)
#pragma unroll
            for (int e = 0; e < 4; e++) d[f][j][e] = 0.f;

    int mr0 = wm * 32 + g;
    int nc0 = wn * 32 + g;

    for (int k0 = 0; k0 < K; k0 += 16) {
        int st = (k0 >> 4) & 1;
        bool more = (k0 + 16) < K;
        // ---- load ALL fragments for this k16 (conflict-free) ----
        unsigned a[2][2][4], bf[2][4][2];
#pragma unroll
        for (int kh = 0; kh < 2; kh++) {
            int kk = kh * 8;
#pragma unroll
            for (int f = 0; f < 2; f++) {
                int mr = mr0 + f * 16;
                a[kh][f][0] = sA[st][kk + tg][mr];
                a[kh][f][1] = sA[st][kk + tg][mr + 8];
                a[kh][f][2] = sA[st][kk + tg + 4][mr];
                a[kh][f][3] = sA[st][kk + tg + 4][mr + 8];
            }
#pragma unroll
            for (int j = 0; j < 4; j++) {
                int nc = nc0 + j * 8;
                bf[kh][j][0] = sB[st][kk + tg][nc];
                bf[kh][j][1] = sB[st][kk + tg + 4][nc];
            }
        }
        // ---- stage next tile: gmem -> regs -> smem (other stage) ----
        if (more) {
            pa0 = *(const float4*)(Ap + k0 + 16);
            pa1 = *(const float4*)(Ap + k0 + 20);
            pb  = *(const float4*)(Bp + k0 + 16);
            int ns = st ^ 1;
            sA[ns][acol + 0][arow] = f2t(pa0.x); sA[ns][acol + 1][arow] = f2t(pa0.y);
            sA[ns][acol + 2][arow] = f2t(pa0.z); sA[ns][acol + 3][arow] = f2t(pa0.w);
            sA[ns][acol + 4][arow] = f2t(pa1.x); sA[ns][acol + 5][arow] = f2t(pa1.y);
            sA[ns][acol + 6][arow] = f2t(pa1.z); sA[ns][acol + 7][arow] = f2t(pa1.w);
            sB[ns][bcol + 0][brow] = f2t(pb.x);  sB[ns][bcol + 1][brow] = f2t(pb.y);
            sB[ns][bcol + 2][brow] = f2t(pb.z);  sB[ns][bcol + 3][brow] = f2t(pb.w);
        }
        // ---- 16 MMAs ----
#pragma unroll
        for (int kh = 0; kh < 2; kh++)
#pragma unroll
            for (int f = 0; f < 2; f++)
#pragma unroll
                for (int j = 0; j < 4; j++)
                    asm volatile(
                        "mma.sync.aligned.m16n8k8.row.col.f32.tf32.tf32.f32 "
                        "{%0,%1,%2,%3}, {%4,%5,%6,%7}, {%8,%9}, {%0,%1,%2,%3};"
                        : "+f"(d[f][j][0]), "+f"(d[f][j][1]),
                          "+f"(d[f][j][2]), "+f"(d[f][j][3])
                        : "r"(a[kh][f][0]), "r"(a[kh][f][1]), "r"(a[kh][f][2]), "r"(a[kh][f][3]),
                          "r"(bf[kh][j][0]), "r"(bf[kh][j][1]));
        __syncthreads();
    }
#pragma unroll
    for (int f = 0; f < 2; f++) {
        int r0 = bm + wm * 32 + f * 16 + g;
#pragma unroll
        for (int j = 0; j < 4; j++) {
            int col = bn + wn * 32 + j * 8 + tg * 2;
            float b0 = __ldg(&bias[col]), b1 = __ldg(&bias[col + 1]);
            float2 v0 = make_float2(d[f][j][0] + b0, d[f][j][1] + b1);
            float2 v1 = make_float2(d[f][j][2] + b0, d[f][j][3] + b1);
            *(float2*)&C[(size_t)r0 * N + col] = v0;
            *(float2*)&C[(size_t)(r0 + 8) * N + col] = v1;
        }
    }
}

// ---------------- small fp32 GEMM (e2d only, M=32, tanh) ----------------
__global__ void __launch_bounds__(256) gemm_atb(
    const float* __restrict__ A, const float* __restrict__ Bm,
    const float* __restrict__ bias, float* __restrict__ C,
    int M, int N, int K, int ldb, int act)
{
    __shared__ float sA[16][68];
    __shared__ float sB[16][68];
    int bm = blockIdx.y * 64, bn = blockIdx.x * 64;
    int tid = threadIdx.x;
    int tm = (tid >> 4) << 2, tn = (tid & 15) << 2;
    int lr = tid >> 2, lc = (tid & 3) << 2;
    float acc[4][4] = {};
    for (int k0 = 0; k0 < K; k0 += 16) {
        float4 a4 = make_float4(0.f, 0.f, 0.f, 0.f);
        if (bm + lr < M) a4 = *(const float4*)&A[(size_t)(bm + lr) * K + k0 + lc];
        sA[lc + 0][lr] = a4.x; sA[lc + 1][lr] = a4.y; sA[lc + 2][lr] = a4.z; sA[lc + 3][lr] = a4.w;
        float4 b4 = *(const float4*)&Bm[(size_t)(bn + lr) * ldb + k0 + lc];
        sB[lc + 0][lr] = b4.x; sB[lc + 1][lr] = b4.y; sB[lc + 2][lr] = b4.z; sB[lc + 3][lr] = b4.w;
        __syncthreads();
#pragma unroll
        for (int kk = 0; kk < 16; kk++) {
            float4 av = *(const float4*)&sA[kk][tm];
            float4 bv = *(const float4*)&sB[kk][tn];
            float a[4] = {av.x, av.y, av.z, av.w};
            float b[4] = {bv.x, bv.y, bv.z, bv.w};
#pragma unroll
            for (int i = 0; i < 4; i++)
#pragma unroll
                for (int j = 0; j < 4; j++) acc[i][j] += a[i] * b[j];
        }
        __syncthreads();
    }
#pragma unroll
    for (int i = 0; i < 4; i++) {
        int row = bm + tm + i;
        if (row >= M) continue;
        float4 v;
        float* pv = &v.x;
#pragma unroll
        for (int j = 0; j < 4; j++) {
            float x = acc[i][j] + bias[bn + tn + j];
            if (act == 1) x = tanhf(x);
            pv[j] = x;
        }
        *(float4*)&C[(size_t)row * N + bn + tn] = v;
    }
}

// ---------------- persistent encoder: 64 CTAs x 256 thr, weights in smem ----------------
__global__ void __launch_bounds__(256) enc_persist(
    const float* __restrict__ Whh_f, const float* __restrict__ Whh_b,
    const float* __restrict__ bhh_f, const float* __restrict__ bhh_b)
{
    extern __shared__ float es[];
    float* swt = es;            // [3*8*256]
    float* sh  = es + 6144;     // [256*33]
    int c = blockIdx.x;
    int dir = c >> 5;
    int ublk = c & 31;
    int tid = threadIdx.x;
    int b = tid & 31;
    int ul = tid >> 5;
    int u = ublk * 8 + ul;
    const float* Whh = dir ? Whh_b : Whh_f;
    const float* bhh = dir ? bhh_b : bhh_f;
    const float* gibase = dir ? g_gib : g_gif;
    for (int i = tid; i < 6144; i += 256) {
        int gate = i >> 11;
        int rem = i & 2047;
        swt[i] = Whh[((size_t)gate * HE + ublk * 8 + (rem >> 8)) * HE + (rem & 255)];
    }
    float br_ = bhh[u], bz_ = bhh[HE + u], bn_ = bhh[2 * HE + u];
    const float4* wr = (const float4*)&swt[(0 * 8 + ul) * 256];
    const float4* wz = (const float4*)&swt[(1 * 8 + ul) * 256];
    const float4* wn = (const float4*)&swt[(2 * 8 + ul) * 256];
    __syncthreads();

    for (int t = 0; t < SS; t++) {
        const float* hprev = g_h[dir][t & 1];
        float* hout = g_h[dir][(t + 1) & 1];
        for (int i = tid; i < BB * HE; i += 256)
            sh[(i & 255) * 33 + (i >> 8)] = __ldcg(&hprev[i]);
        __syncthreads();
        float ar = 0.f, az = 0.f, an = 0.f;
#pragma unroll 8
        for (int k4 = 0; k4 < 64; k4++) {
            int k = k4 * 4;
            float h0 = sh[(k + 0) * 33 + b], h1 = sh[(k + 1) * 33 + b];
            float h2 = sh[(k + 2) * 33 + b], h3 = sh[(k + 3) * 33 + b];
            float4 ww;
            ww = wr[k4]; ar += h0 * ww.x + h1 * ww.y + h2 * ww.z + h3 * ww.w;
            ww = wz[k4]; az += h0 * ww.x + h1 * ww.y + h2 * ww.z + h3 * ww.w;
            ww = wn[k4]; an += h0 * ww.x + h1 * ww.y + h2 * ww.z + h3 * ww.w;
        }
        int s = dir ? (SS - 1 - t) : t;
        const float* gi = gibase + (size_t)(s * BB + b) * (3 * HE);
        float ghr = ar + br_, ghz = az + bz_, ghn = an + bn_;
        float r = 1.f / (1.f + expf(-(__ldg(&gi[u]) + ghr)));
        float z = 1.f / (1.f + expf(-(__ldg(&gi[HE + u]) + ghz)));
        float n = tanhf(__ldg(&gi[2 * HE + u]) + r * ghn);
        float hp = sh[u * 33 + b];
        float hn2 = (1.f - z) * n + z * hp;
        hout[b * HE + u] = hn2;
        g_enhy[((size_t)b * SS + s) * (2 * HE) + dir * HE + u] = hn2;
        grid_bar(dir, (unsigned)(t + 1), 32u);
    }
}

// ---------------- build [hT_f, hT_b] ----------------
__global__ void hcat_kernel() {
    int i = blockIdx.x * blockDim.x + threadIdx.x;
    if (i >= BB * 2 * HE) return;
    int b = i >> 9;
    int j = i & 511;
    float v;
    if (j < HE) v = g_enhy[((size_t)b * SS + (SS - 1)) * (2 * HE) + j];
    else        v = g_enhy[((size_t)b * SS + 0) * (2 * HE) + j];
    g_hcat[i] = v;
}

// ---------------- persistent decoder: 128 CTAs x 512 thr ----------------
__global__ void __launch_bounds__(512) dec_persist(
    const float* __restrict__ dWih, const float* __restrict__ dWhh,
    const float* __restrict__ dbhh)
{
    extern __shared__ float sm[];
    float* swd = sm;                    // [12288]
    float* shh = sm + 12288;            // [512*33]
    float* shc = shh + 16896;           // [512*33]
    float* smx = shc + 16896;           // [9*132]
    float* sm_m   = sm + 12288;
    float* sm_l   = sm_m + 16;
    float* sm_ctx = sm_l + 16;

    int c = blockIdx.x;
    int tid = threadIdx.x;
    int lane = tid & 31, w = tid >> 5;
    int ab = c & 31, chunk = c >> 5, s0 = chunk * (SS / 4);
    int gb = tid & 31;
    int slot = (tid >> 5) & 3;
    int which = tid >> 7;
    int gu = c * 4 + slot;

    for (int i = tid; i < 12288; i += 512) {
        int sg = i >> 11;
        int rem = i & 2047;
        int sl = rem >> 9;
        int k = rem & 511;
        int s_ = sg / 3, g2 = sg % 3;
        int uu = c * 4 + sl;
        swd[i] = (s_ == 0) ? dWhh[((size_t)g2 * HD + uu) * HD + k]
                           : dWih[((size_t)(g2 * HD + uu)) * 768 + 256 + k];
    }
    int ws = which >> 1;
    int kb = (which & 1) * 256;
    const float4* vr = (const float4*)&swd[((ws * 3 + 0) * 4 + slot) * 512 + kb];
    const float4* vz = (const float4*)&swd[((ws * 3 + 1) * 4 + slot) * 512 + kb];
    const float4* vn = (const float4*)&swd[((ws * 3 + 2) * 4 + slot) * 512 + kb];
    float db_r = dbhh[gu], db_z = dbhh[HD + gu], db_n = dbhh[2 * HD + gu];
    __syncthreads();

    for (int t = 0; t < TT; t++) {
        const float* hcur = g_hdec[t & 1];
        // ---------- Phase A ----------
        {
            const float* hd = hcur + ab * HD;
            float4 hreg[4];
#pragma unroll
            for (int j = 0; j < 4; j++)
                hreg[j] = __ldcg((const float4*)(hd + (j * 32 + lane) * 4));
            const float* eb = g_enhy + (size_t)ab * SS * HD;
            float m = -1e30f, l = 0.f;
            float4 cacc[4];
#pragma unroll
            for (int j = 0; j < 4; j++) cacc[j] = make_float4(0.f, 0.f, 0.f, 0.f);
            for (int s = s0 + w; s < s0 + SS / 4; s += 16) {
                const float4* e4 = (const float4*)(eb + (size_t)s * HD);
                float4 ev[4];
                float acc = 0.f;
#pragma unroll
                for (int j = 0; j < 4; j++) {
                    ev[j] = __ldg(&e4[j * 32 + lane]);
                    acc += ev[j].x * hreg[j].x + ev[j].y * hreg[j].y
                         + ev[j].z * hreg[j].z + ev[j].w * hreg[j].w;
                }
#pragma unroll
                for (int o = 16; o; o >>= 1) acc += __shfl_xor_sync(0xffffffffu, acc, o);
                float mnew = fmaxf(m, acc);
                float scale = __expf(m - mnew);
                float p = __expf(acc - mnew);
                l = l * scale + p;
#pragma unroll
                for (int j = 0; j < 4; j++) {
                    cacc[j].x = cacc[j].x * scale + p * ev[j].x;
                    cacc[j].y = cacc[j].y * scale + p * ev[j].y;
                    cacc[j].z = cacc[j].z * scale + p * ev[j].z;
                    cacc[j].w = cacc[j].w * scale + p * ev[j].w;
                }
                m = mnew;
            }
            if (lane == 0) { sm_m[w] = m; sm_l[w] = l; }
#pragma unroll
            for (int j = 0; j < 4; j++)
                ((float4*)(sm_ctx + w * HD))[j * 32 + lane] = cacc[j];
            __syncthreads();
            float M = -1e30f;
#pragma unroll
            for (int q = 0; q < 16; q++) M = fmaxf(M, sm_m[q]);
            float L = 0.f, vv = 0.f;
            int e = tid;
#pragma unroll
            for (int q = 0; q < 16; q++) {
                float f_ = __expf(sm_m[q] - M);
                L += sm_l[q] * f_;
                vv += sm_ctx[q * HD + e] * f_;
            }
            g_attc[chunk][ab][e] = vv;
            if (tid == 0) { g_attm[chunk][ab] = M; g_attl[chunk][ab] = L; }
        }
        grid_bar(2, (unsigned)(3 * t + 1), 128u);
        // ---------- Phase R ----------
        if (tid < 128) {
            int idx = c * 128 + tid;
            int b2 = idx >> 9, e = idx & 511;
            float m0 = __ldcg(&g_attm[0][b2]), m1 = __ldcg(&g_attm[1][b2]);
            float m2 = __ldcg(&g_attm[2][b2]), m3 = __ldcg(&g_attm[3][b2]);
            float M = fmaxf(fmaxf(m0, m1), fmaxf(m2, m3));
            float f0 = __expf(m0 - M), f1 = __expf(m1 - M);
            float f2 = __expf(m2 - M), f3 = __expf(m3 - M);
            float L = __ldcg(&g_attl[0][b2]) * f0 + __ldcg(&g_attl[1][b2]) * f1
                    + __ldcg(&g_attl[2][b2]) * f2 + __ldcg(&g_attl[3][b2]) * f3;
            float v = __ldcg(&g_attc[0][b2][e]) * f0 + __ldcg(&g_attc[1][b2][e]) * f1
                    + __ldcg(&g_attc[2][b2][e]) * f2 + __ldcg(&g_attc[3][b2][e]) * f3;
            g_ctx[b2 * HD + e] = tanhf(v / L);
        }
        grid_bar(2, (unsigned)(3 * t + 2), 128u);
        // ---------- Phase G ----------
        {
            for (int i = tid; i < BB * HD; i += 512) {
                int b2 = i >> 9, k = i & 511;
                shh[k * 33 + b2] = __ldcg(&hcur[i]);
                shc[k * 33 + b2] = __ldcg(&g_ctx[i]);
            }
            __syncthreads();
            const float* src = ws ? shc : shh;
            float ar = 0.f, az = 0.f, an = 0.f;
#pragma unroll 8
            for (int k4 = 0; k4 < 64; k4++) {
                int k = kb + k4 * 4;
                float h0 = src[(k + 0) * 33 + gb], h1 = src[(k + 1) * 33 + gb];
                float h2 = src[(k + 2) * 33 + gb], h3 = src[(k + 3) * 33 + gb];
                float4 ww;
                ww = vr[k4]; ar += h0 * ww.x + h1 * ww.y + h2 * ww.z + h3 * ww.w;
                ww = vz[k4]; az += h0 * ww.x + h1 * ww.y + h2 * ww.z + h3 * ww.w;
                ww = vn[k4]; an += h0 * ww.x + h1 * ww.y + h2 * ww.z + h3 * ww.w;
            }
            int p = tid & 127;
            if (which != 0) {
                smx[((which - 1) * 3 + 0) * 132 + p] = ar;
                smx[((which - 1) * 3 + 1) * 132 + p] = az;
                smx[((which - 1) * 3 + 2) * 132 + p] = an;
            }
            __syncthreads();
            if (which == 0) {
                float ar2 = ar + smx[0 * 132 + p];
                float az2 = az + smx[1 * 132 + p];
                float an2 = an + smx[2 * 132 + p];
                float cr = smx[3 * 132 + p] + smx[6 * 132 + p];
                float cz = smx[4 * 132 + p] + smx[7 * 132 + p];
                float cn = smx[5 * 132 + p] + smx[8 * 132 + p];
                const float* gi = g_gidec + ((size_t)t * BB + gb) * (3 * HD);
                float ghr = ar2 + db_r, ghz = az2 + db_z, ghn = an2 + db_n;
                float r = 1.f / (1.f + expf(-(__ldg(&gi[gu]) + cr + ghr)));
                float z = 1.f / (1.f + expf(-(__ldg(&gi[HD + gu]) + cz + ghz)));
                float n = tanhf(__ldg(&gi[2 * HD + gu]) + cn + r * ghn);
                float hp = shh[gu * 33 + gb];
                float hn2 = (1.f - z) * n + z * hp;
                g_hdec[(t + 1) & 1][gb * HD + gu] = hn2;
                g_decout[((size_t)gb * TT + t) * HD + gu] = hn2;
            }
        }
        grid_bar(2, (unsigned)(3 * t + 3), 128u);
    }
}

// ---------------- host ----------------
extern "C" void kernel_launch(void* const* d_in, const int* in_sizes, int n_in,
                              void* d_out, int out_size) {
    const int*   src_ids = (const int*)d_in[0];
    const int*   trg_ids = (const int*)d_in[1];
    const float* src_emb = (const float*)d_in[2];
    const float* trg_emb = (const float*)d_in[3];
    const float* eWihf   = (const float*)d_in[4];
    const float* eWhhf   = (const float*)d_in[5];
    const float* ebihf   = (const float*)d_in[6];
    const float* ebhhf   = (const float*)d_in[7];
    const float* eWihb   = (const float*)d_in[8];
    const float* eWhhb   = (const float*)d_in[9];
    const float* ebihb   = (const float*)d_in[10];
    const float* ebhhb   = (const float*)d_in[11];
    const float* e2dW    = (const float*)d_in[12];
    const float* e2db    = (const float*)d_in[13];
    const float* dWih    = (const float*)d_in[14];
    const float* dWhh    = (const float*)d_in[15];
    const float* dbih    = (const float*)d_in[16];
    const float* dbhh    = (const float*)d_in[17];
    const float* outW    = (const float*)d_in[18];
    const float* outb    = (const float*)d_in[19];
    float* out = (float*)d_out;

    const int ENC_SMEM = (6144 + HE * 33) * (int)sizeof(float);
    const int DEC_SMEM = (12288 + 2 * HD * 33 + 9 * 132) * (int)sizeof(float);
    cudaFuncSetAttribute(enc_persist, cudaFuncAttributeMaxDynamicSharedMemorySize, ENC_SMEM);
    cudaFuncSetAttribute(dec_persist, cudaFuncAttributeMaxDynamicSharedMemorySize, DEC_SMEM);

    float *p_srcx, *p_trgx, *p_gif, *p_gib, *p_gidec, *p_hcat, *p_hdec, *p_decout;
    cudaGetSymbolAddress((void**)&p_srcx, g_srcx);
    cudaGetSymbolAddress((void**)&p_trgx, g_trgx);
    cudaGetSymbolAddress((void**)&p_gif, g_gif);
    cudaGetSymbolAddress((void**)&p_gib, g_gib);
    cudaGetSymbolAddress((void**)&p_gidec, g_gidec);
    cudaGetSymbolAddress((void**)&p_hcat, g_hcat);
    cudaGetSymbolAddress((void**)&p_hdec, g_hdec);
    cudaGetSymbolAddress((void**)&p_decout, g_decout);

    // 1) embeddings + prep
    embed_kernel<<<(SS * BB * (EE / 4) + 255) / 256, 256>>>(src_ids, src_emb, p_srcx, SS);
    embed_kernel<<<(TT * BB * (EE / 4) + 255) / 256, 256>>>(trg_ids, trg_emb, p_trgx, TT);
    prep_kernel<<<(2 * BB * HE + 255) / 256, 256>>>();

    // 2) time-parallel input-side GRU GEMMs (tf32 tensor cores)
    gemm_tf32<<<dim3(768 / 64, SS * BB / 128), 256>>>(p_srcx, eWihf, ebihf, p_gif, SS * BB, 768, 256, 256);
    gemm_tf32<<<dim3(768 / 64, SS * BB / 128), 256>>>(p_srcx, eWihb, ebihb, p_gib, SS * BB, 768, 256, 256);
    gemm_tf32<<<dim3(1536 / 64, TT * BB / 128), 256>>>(p_trgx, dWih, dbih, p_gidec, TT * BB, 1536, 256, 768);

    // 3) persistent encoder scan
    enc_persist<<<64, 256, ENC_SMEM>>>(eWhhf, eWhhb, ebhhf, ebhhb);

    // 4) h0 = tanh([hT_f,hT_b] @ e2d_W.T + e2d_b)
    hcat_kernel<<<(BB * 2 * HE + 255) / 256, 256>>>();
    gemm_atb<<<dim3(512 / 64, 1), 256>>>(p_hcat, e2dW, e2db, p_hdec, BB, 512, 512, 512, 1);

    // 5) persistent decoder scan
    dec_persist<<<128, 512, DEC_SMEM>>>(dWih, dWhh, dbhh);

    // 6) logits = dec_out @ out_W.T + out_b (tf32 tensor cores)
    gemm_tf32<<<dim3(VV / 64, BB * TT / 128), 256>>>(p_decout, outW, outb, out, BB * TT, VV, 512, 512);
}

// round 6
// speedup vs baseline: 2.6279x; 1.0505x over previous
#include <cuda_runtime.h>
#include <math.h>

#define BB 32
#define SS 400
#define TT 100
#define EE 256
#define HE 256
#define HD 512
#define VV 32000

// ---------------- scratch (device globals; no allocations) ----------------
__device__ float g_srcx[SS * BB * EE];
__device__ float g_trgx[TT * BB * EE];
__device__ float g_gif[SS * BB * 3 * HE];
__device__ float g_gib[SS * BB * 3 * HE];
__device__ float g_gidec[TT * BB * 3 * HD];
__device__ float g_enhy[BB * SS * 2 * HE];
__device__ float g_hT[2][2][HE * BB];     // [dir][parity][u*BB + b] (transposed)
__device__ float g_hcat[BB * 2 * HE];
__device__ float g_hdec[2][BB * HD];
__device__ float g_ctx[BB * HD];
__device__ float g_decout[BB * TT * HD];
__device__ float g_attm[4][BB];
__device__ float g_attl[4][BB];
__device__ float g_attc[4][BB][HD];
__device__ unsigned g_bar_cnt[4];         // monotonic counters: 0=enc dir0, 1=enc dir1, 2=dec

// ---------------- cheap monotonic grid barrier ----------------
// CTA-wide: sync, one release-arrive by tid0, every thread acquire-polls counter.
__device__ __forceinline__ void bar_sync(unsigned* cnt, unsigned target) {
    __syncthreads();
    if (threadIdx.x == 0) {
        unsigned p;
        asm volatile("atom.release.gpu.global.add.u32 %0,[%1],%2;"
                     : "=r"(p) : "l"(cnt), "r"(1u) : "memory");
    }
    unsigned v;
    do {
        asm volatile("ld.acquire.gpu.global.u32 %0,[%1];" : "=r"(v) : "l"(cnt) : "memory");
    } while (v < target);
}

// ---------------- embedding gather ----------------
__global__ void embed_kernel(const int* __restrict__ ids, const float* __restrict__ table,
                             float* __restrict__ out, int seq) {
    int i = blockIdx.x * blockDim.x + threadIdx.x;
    int E4 = EE / 4;
    int total = seq * BB * E4;
    if (i >= total) return;
    int e4 = i % E4;
    int sb = i / E4;
    int b = sb % BB;
    int s = sb / BB;
    int id = ids[b * seq + s];
    ((float4*)out)[i] = ((const float4*)table)[(size_t)id * E4 + e4];
}

// ---------------- prep ----------------
__global__ void prep_kernel() {
    int i = blockIdx.x * blockDim.x + threadIdx.x;
    if (i < 4) g_bar_cnt[i] = 0u;
    if (i < 2 * BB * HE) g_hT[i / (BB * HE)][0][i % (BB * HE)] = 0.f;
}

// ---------------- tf32 -> bits ----------------
__device__ __forceinline__ unsigned f2t(float x) {
    unsigned r; asm("cvt.rna.tf32.f32 %0, %1;" : "=r"(r) : "f"(x)); return r;
}

// ---------------- tf32 tensor-core GEMM v3: 3-stage pipeline ----------------
// C = A(M,K)*B(N,K)^T + bias. 128x64 tile, 256 thr (8 warps, warp tile 32x32).
// Prefetch distance 2: LDG(i+2), STS(i+1), MMA(i) each iteration.
__global__ void __launch_bounds__(256) gemm_tf32(
    const float* __restrict__ A, const float* __restrict__ Bm,
    const float* __restrict__ bias, float* __restrict__ C,
    int M, int N, int K, int ldb)
{
    __shared__ unsigned sA[3][16][136];
    __shared__ unsigned sB[3][16][72];
    int bm = blockIdx.y * 128, bn = blockIdx.x * 64;
    int tid = threadIdx.x;
    int w = tid >> 5, lane = tid & 31;
    int wm = w & 3, wn = w >> 2;
    int g = lane >> 2, tg = lane & 3;
    int arow = tid >> 1, acol = (tid & 1) * 8;
    int brow = tid >> 2, bcol = (tid & 3) * 4;
    const float* Ap = A + (size_t)(bm + arow) * K + acol;
    const float* Bp = Bm + (size_t)(bn + brow) * ldb + bcol;
    int nt = K >> 4;

    // tile 0 -> stage 0
    {
        float4 a0 = *(const float4*)Ap;
        float4 a1 = *(const float4*)(Ap + 4);
        float4 b0 = *(const float4*)Bp;
        sA[0][acol + 0][arow] = f2t(a0.x); sA[0][acol + 1][arow] = f2t(a0.y);
        sA[0][acol + 2][arow] = f2t(a0.z); sA[0][acol + 3][arow] = f2t(a0.w);
        sA[0][acol + 4][arow] = f2t(a1.x); sA[0][acol + 5][arow] = f2t(a1.y);
        sA[0][acol + 6][arow] = f2t(a1.z); sA[0][acol + 7][arow] = f2t(a1.w);
        sB[0][bcol + 0][brow] = f2t(b0.x); sB[0][bcol + 1][brow] = f2t(b0.y);
        sB[0][bcol + 2][brow] = f2t(b0.z); sB[0][bcol + 3][brow] = f2t(b0.w);
    }
    // tile 1 -> regs
    float4 pa0, pa1, pb;
    if (nt > 1) {
        pa0 = *(const float4*)(Ap + 16);
        pa1 = *(const float4*)(Ap + 20);
        pb  = *(const float4*)(Bp + 16);
    }
    __syncthreads();

    float d[2][4][4];
#pragma unroll
    for (int f = 0; f < 2; f++)
#pragma unroll
        for (int j = 0; j < 4; j++)
#pragma unroll
            for (int e = 0; e < 4; e++) d[f][j][e] = 0.f;

    int mr0 = wm * 32 + g;
    int nc0 = wn * 32 + g;
    int st = 0;

    for (int i = 0; i < nt; i++) {
        // ---- fragments for tile i from stage st ----
        unsigned a[2][2][4], bf[2][4][2];
#pragma unroll
        for (int kh = 0; kh < 2; kh++) {
            int kk = kh * 8;
#pragma unroll
            for (int f = 0; f < 2; f++) {
                int mr = mr0 + f * 16;
                a[kh][f][0] = sA[st][kk + tg][mr];
                a[kh][f][1] = sA[st][kk + tg][mr + 8];
                a[kh][f][2] = sA[st][kk + tg + 4][mr];
                a[kh][f][3] = sA[st][kk + tg + 4][mr + 8];
            }
#pragma unroll
            for (int j = 0; j < 4; j++) {
                int nc = nc0 + j * 8;
                bf[kh][j][0] = sB[st][kk + tg][nc];
                bf[kh][j][1] = sB[st][kk + tg + 4][nc];
            }
        }
        // ---- STS tile i+1 (regs loaded last iteration / preloaded) ----
        if (i + 1 < nt) {
            int ns = st + 1; if (ns == 3) ns = 0;
            sA[ns][acol + 0][arow] = f2t(pa0.x); sA[ns][acol + 1][arow] = f2t(pa0.y);
            sA[ns][acol + 2][arow] = f2t(pa0.z); sA[ns][acol + 3][arow] = f2t(pa0.w);
            sA[ns][acol + 4][arow] = f2t(pa1.x); sA[ns][acol + 5][arow] = f2t(pa1.y);
            sA[ns][acol + 6][arow] = f2t(pa1.z); sA[ns][acol + 7][arow] = f2t(pa1.w);
            sB[ns][bcol + 0][brow] = f2t(pb.x);  sB[ns][bcol + 1][brow] = f2t(pb.y);
            sB[ns][bcol + 2][brow] = f2t(pb.z);  sB[ns][bcol + 3][brow] = f2t(pb.w);
        }
        // ---- LDG tile i+2 ----
        if (i + 2 < nt) {
            int k = (i + 2) << 4;
            pa0 = *(const float4*)(Ap + k);
            pa1 = *(const float4*)(Ap + k + 4);
            pb  = *(const float4*)(Bp + k);
        }
        // ---- 16 MMAs ----
#pragma unroll
        for (int kh = 0; kh < 2; kh++)
#pragma unroll
            for (int f = 0; f < 2; f++)
#pragma unroll
                for (int j = 0; j < 4; j++)
                    asm volatile(
                        "mma.sync.aligned.m16n8k8.row.col.f32.tf32.tf32.f32 "
                        "{%0,%1,%2,%3}, {%4,%5,%6,%7}, {%8,%9}, {%0,%1,%2,%3};"
                        : "+f"(d[f][j][0]), "+f"(d[f][j][1]),
                          "+f"(d[f][j][2]), "+f"(d[f][j][3])
                        : "r"(a[kh][f][0]), "r"(a[kh][f][1]), "r"(a[kh][f][2]), "r"(a[kh][f][3]),
                          "r"(bf[kh][j][0]), "r"(bf[kh][j][1]));
        st = st + 1; if (st == 3) st = 0;
        __syncthreads();
    }
#pragma unroll
    for (int f = 0; f < 2; f++) {
        int r0 = bm + wm * 32 + f * 16 + g;
#pragma unroll
        for (int j = 0; j < 4; j++) {
            int col = bn + wn * 32 + j * 8 + tg * 2;
            float b0 = __ldg(&bias[col]), b1 = __ldg(&bias[col + 1]);
            float2 v0 = make_float2(d[f][j][0] + b0, d[f][j][1] + b1);
            float2 v1 = make_float2(d[f][j][2] + b0, d[f][j][3] + b1);
            *(float2*)&C[(size_t)r0 * N + col] = v0;
            *(float2*)&C[(size_t)(r0 + 8) * N + col] = v1;
        }
    }
}

// ---------------- small fp32 GEMM (e2d only, M=32, tanh) ----------------
__global__ void __launch_bounds__(256) gemm_atb(
    const float* __restrict__ A, const float* __restrict__ Bm,
    const float* __restrict__ bias, float* __restrict__ C,
    int M, int N, int K, int ldb, int act)
{
    __shared__ float sA[16][68];
    __shared__ float sB[16][68];
    int bm = blockIdx.y * 64, bn = blockIdx.x * 64;
    int tid = threadIdx.x;
    int tm = (tid >> 4) << 2, tn = (tid & 15) << 2;
    int lr = tid >> 2, lc = (tid & 3) << 2;
    float acc[4][4] = {};
    for (int k0 = 0; k0 < K; k0 += 16) {
        float4 a4 = make_float4(0.f, 0.f, 0.f, 0.f);
        if (bm + lr < M) a4 = *(const float4*)&A[(size_t)(bm + lr) * K + k0 + lc];
        sA[lc + 0][lr] = a4.x; sA[lc + 1][lr] = a4.y; sA[lc + 2][lr] = a4.z; sA[lc + 3][lr] = a4.w;
        float4 b4 = *(const float4*)&Bm[(size_t)(bn + lr) * ldb + k0 + lc];
        sB[lc + 0][lr] = b4.x; sB[lc + 1][lr] = b4.y; sB[lc + 2][lr] = b4.z; sB[lc + 3][lr] = b4.w;
        __syncthreads();
#pragma unroll
        for (int kk = 0; kk < 16; kk++) {
            float4 av = *(const float4*)&sA[kk][tm];
            float4 bv = *(const float4*)&sB[kk][tn];
            float a[4] = {av.x, av.y, av.z, av.w};
            float b[4] = {bv.x, bv.y, bv.z, bv.w};
#pragma unroll
            for (int i = 0; i < 4; i++)
#pragma unroll
                for (int j = 0; j < 4; j++) acc[i][j] += a[i] * b[j];
        }
        __syncthreads();
    }
#pragma unroll
    for (int i = 0; i < 4; i++) {
        int row = bm + tm + i;
        if (row >= M) continue;
        float4 v;
        float* pv = &v.x;
#pragma unroll
        for (int j = 0; j < 4; j++) {
            float x = acc[i][j] + bias[bn + tn + j];
            if (act == 1) x = tanhf(x);
            pv[j] = x;
        }
        *(float4*)&C[(size_t)row * N + bn + tn] = v;
    }
}

// ---------------- persistent encoder: 64 CTAs x 256 thr ----------------
// h transposed in gmem [u][b]; smem h in [b][k] stride 260 (conflict-free f4).
__global__ void __launch_bounds__(256) enc_persist(
    const float* __restrict__ Whh_f, const float* __restrict__ Whh_b,
    const float* __restrict__ bhh_f, const float* __restrict__ bhh_b)
{
    extern __shared__ float es[];
    float* swt = es;            // [3*8*256] this CTA's 8-unit weights
    float* sh  = es + 6144;     // [32][260] h per batch, f4-conflict-free (65 odd)
    int c = blockIdx.x;
    int dir = c >> 5;
    int ublk = c & 31;
    int tid = threadIdx.x;
    int b = tid & 31;
    int ul = tid >> 5;
    int u = ublk * 8 + ul;
    const float* Whh = dir ? Whh_b : Whh_f;
    const float* bhh = dir ? bhh_b : bhh_f;
    const float* gibase = dir ? g_gib : g_gif;
    for (int i = tid; i < 6144; i += 256) {
        int gate = i >> 11;
        int rem = i & 2047;
        swt[i] = Whh[((size_t)gate * HE + ublk * 8 + (rem >> 8)) * HE + (rem & 255)];
    }
    float br_ = bhh[u], bz_ = bhh[HE + u], bn_ = bhh[2 * HE + u];
    const float4* wr = (const float4*)&swt[(0 * 8 + ul) * 256];
    const float4* wz = (const float4*)&swt[(1 * 8 + ul) * 256];
    const float4* wn = (const float4*)&swt[(2 * 8 + ul) * 256];
    unsigned* cnt = &g_bar_cnt[dir];
    const float* hb = sh + b * 260;

    for (int t = 0; t < SS; t++) {
        if (t > 0) bar_sync(cnt, (unsigned)(32 * t));
        // fill sh[b][k] from g_hT (coalesced loads, 4-way-conflict scalar stores)
        const float* hsrc = g_hT[dir][t & 1];
        for (int i = tid; i < BB * HE; i += 256)
            sh[(i & 31) * 260 + (i >> 5)] = __ldcg(&hsrc[i]);
        __syncthreads();
        float ar = 0.f, az = 0.f, an = 0.f;
#pragma unroll 8
        for (int k4 = 0; k4 < 64; k4++) {
            float4 h4 = *(const float4*)(hb + k4 * 4);
            float4 ww;
            ww = wr[k4]; ar += h4.x * ww.x + h4.y * ww.y + h4.z * ww.z + h4.w * ww.w;
            ww = wz[k4]; az += h4.x * ww.x + h4.y * ww.y + h4.z * ww.z + h4.w * ww.w;
            ww = wn[k4]; an += h4.x * ww.x + h4.y * ww.y + h4.z * ww.z + h4.w * ww.w;
        }
        int s = dir ? (SS - 1 - t) : t;
        const float* gi = gibase + (size_t)(s * BB + b) * (3 * HE);
        float ghr = ar + br_, ghz = az + bz_, ghn = an + bn_;
        float r = 1.f / (1.f + expf(-(__ldg(&gi[u]) + ghr)));
        float z = 1.f / (1.f + expf(-(__ldg(&gi[HE + u]) + ghz)));
        float n = tanhf(__ldg(&gi[2 * HE + u]) + r * ghn);
        float hp = hb[u];
        float hn2 = (1.f - z) * n + z * hp;
        g_hT[dir][(t + 1) & 1][u * BB + b] = hn2;   // coalesced (lanes = b)
        g_enhy[((size_t)b * SS + s) * (2 * HE) + dir * HE + u] = hn2;
        __syncthreads();   // all reads of sh done before next iteration's arrive
    }
}

// ---------------- build [hT_f, hT_b] ----------------
__global__ void hcat_kernel() {
    int i = blockIdx.x * blockDim.x + threadIdx.x;
    if (i >= BB * 2 * HE) return;
    int b = i >> 9;
    int j = i & 511;
    float v;
    if (j < HE) v = g_enhy[((size_t)b * SS + (SS - 1)) * (2 * HE) + j];
    else        v = g_enhy[((size_t)b * SS + 0) * (2 * HE) + j];
    g_hcat[i] = v;
}

// ---------------- persistent decoder: 128 CTAs x 512 thr ----------------
__global__ void __launch_bounds__(512) dec_persist(
    const float* __restrict__ dWih, const float* __restrict__ dWhh,
    const float* __restrict__ dbhh)
{
    extern __shared__ float sm[];
    float* swd = sm;                    // [12288] weights
    float* shh = sm + 12288;            // [32][516] h (129 odd -> f4 conflict-free)
    float* shc = shh + 16512;           // [32][516] ctx
    float* smx = shc + 16512;           // [9*132]
    float* sm_m   = sm + 12288;         // phase A overlay
    float* sm_l   = sm_m + 16;
    float* sm_ctx = sm_l + 16;

    int c = blockIdx.x;
    int tid = threadIdx.x;
    int lane = tid & 31, w = tid >> 5;
    int ab = c & 31, chunk = c >> 5, s0 = chunk * (SS / 4);
    int gb = tid & 31;
    int slot = (tid >> 5) & 3;
    int which = tid >> 7;
    int gu = c * 4 + slot;

    for (int i = tid; i < 12288; i += 512) {
        int sg = i >> 11;
        int rem = i & 2047;
        int sl = rem >> 9;
        int k = rem & 511;
        int s_ = sg / 3, g2 = sg % 3;
        int uu = c * 4 + sl;
        swd[i] = (s_ == 0) ? dWhh[((size_t)g2 * HD + uu) * HD + k]
                           : dWih[((size_t)(g2 * HD + uu)) * 768 + 256 + k];
    }
    int ws = which >> 1;
    int kb = (which & 1) * 256;
    const float4* vr = (const float4*)&swd[((ws * 3 + 0) * 4 + slot) * 512 + kb];
    const float4* vz = (const float4*)&swd[((ws * 3 + 1) * 4 + slot) * 512 + kb];
    const float4* vn = (const float4*)&swd[((ws * 3 + 2) * 4 + slot) * 512 + kb];
    float db_r = dbhh[gu], db_z = dbhh[HD + gu], db_n = dbhh[2 * HD + gu];
    unsigned* cnt = &g_bar_cnt[2];
    __syncthreads();

    for (int t = 0; t < TT; t++) {
        const float* hcur = g_hdec[t & 1];
        // ---------- Phase A: flash attention partials ----------
        {
            const float* hd = hcur + ab * HD;
            float4 hreg[4];
#pragma unroll
            for (int j = 0; j < 4; j++)
                hreg[j] = __ldcg((const float4*)(hd + (j * 32 + lane) * 4));
            const float* eb = g_enhy + (size_t)ab * SS * HD;
            float m = -1e30f, l = 0.f;
            float4 cacc[4];
#pragma unroll
            for (int j = 0; j < 4; j++) cacc[j] = make_float4(0.f, 0.f, 0.f, 0.f);
            for (int s = s0 + w; s < s0 + SS / 4; s += 16) {
                const float4* e4 = (const float4*)(eb + (size_t)s * HD);
                float4 ev[4];
                float acc = 0.f;
#pragma unroll
                for (int j = 0; j < 4; j++) {
                    ev[j] = __ldg(&e4[j * 32 + lane]);
                    acc += ev[j].x * hreg[j].x + ev[j].y * hreg[j].y
                         + ev[j].z * hreg[j].z + ev[j].w * hreg[j].w;
                }
#pragma unroll
                for (int o = 16; o; o >>= 1) acc += __shfl_xor_sync(0xffffffffu, acc, o);
                float mnew = fmaxf(m, acc);
                float scale = __expf(m - mnew);
                float p = __expf(acc - mnew);
                l = l * scale + p;
#pragma unroll
                for (int j = 0; j < 4; j++) {
                    cacc[j].x = cacc[j].x * scale + p * ev[j].x;
                    cacc[j].y = cacc[j].y * scale + p * ev[j].y;
                    cacc[j].z = cacc[j].z * scale + p * ev[j].z;
                    cacc[j].w = cacc[j].w * scale + p * ev[j].w;
                }
                m = mnew;
            }
            if (lane == 0) { sm_m[w] = m; sm_l[w] = l; }
#pragma unroll
            for (int j = 0; j < 4; j++)
                ((float4*)(sm_ctx + w * HD))[j * 32 + lane] = cacc[j];
            __syncthreads();
            float M = -1e30f;
#pragma unroll
            for (int q = 0; q < 16; q++) M = fmaxf(M, sm_m[q]);
            float L = 0.f, vv = 0.f;
            int e = tid;
#pragma unroll
            for (int q = 0; q < 16; q++) {
                float f_ = __expf(sm_m[q] - M);
                L += sm_l[q] * f_;
                vv += sm_ctx[q * HD + e] * f_;
            }
            g_attc[chunk][ab][e] = vv;
            if (tid == 0) { g_attm[chunk][ab] = M; g_attl[chunk][ab] = L; }
        }
        bar_sync(cnt, (unsigned)(128 * (3 * t + 1)));
        // ---------- Phase R: distributed combine ----------
        if (tid < 128) {
            int idx = c * 128 + tid;
            int b2 = idx >> 9, e = idx & 511;
            float m0 = __ldcg(&g_attm[0][b2]), m1 = __ldcg(&g_attm[1][b2]);
            float m2 = __ldcg(&g_attm[2][b2]), m3 = __ldcg(&g_attm[3][b2]);
            float M = fmaxf(fmaxf(m0, m1), fmaxf(m2, m3));
            float f0 = __expf(m0 - M), f1 = __expf(m1 - M);
            float f2 = __expf(m2 - M), f3 = __expf(m3 - M);
            float L = __ldcg(&g_attl[0][b2]) * f0 + __ldcg(&g_attl[1][b2]) * f1
                    + __ldcg(&g_attl[2][b2]) * f2 + __ldcg(&g_attl[3][b2]) * f3;
            float v = __ldcg(&g_attc[0][b2][e]) * f0 + __ldcg(&g_attc[1][b2][e]) * f1
                    + __ldcg(&g_attc[2][b2][e]) * f2 + __ldcg(&g_attc[3][b2][e]) * f3;
            g_ctx[b2 * HD + e] = tanhf(v / L);
        }
        bar_sync(cnt, (unsigned)(128 * (3 * t + 2)));
        // ---------- Phase G: GRU step ----------
        {
            // fill shh/shc in [b][k] stride 516 (coalesced f4 loads, conflict-free f4 stores)
            for (int i4 = tid; i4 < BB * HD / 4; i4 += 512) {
                int b2 = i4 >> 7, k = (i4 & 127) * 4;
                *(float4*)&shh[b2 * 516 + k] = __ldcg((const float4*)&hcur[i4 * 4]);
                *(float4*)&shc[b2 * 516 + k] = __ldcg((const float4*)&g_ctx[i4 * 4]);
            }
            __syncthreads();
            const float* src = (ws ? shc : shh) + gb * 516 + kb;
            float ar = 0.f, az = 0.f, an = 0.f;
#pragma unroll 8
            for (int k4 = 0; k4 < 64; k4++) {
                float4 h4 = *(const float4*)(src + k4 * 4);
                float4 ww;
                ww = vr[k4]; ar += h4.x * ww.x + h4.y * ww.y + h4.z * ww.z + h4.w * ww.w;
                ww = vz[k4]; az += h4.x * ww.x + h4.y * ww.y + h4.z * ww.z + h4.w * ww.w;
                ww = vn[k4]; an += h4.x * ww.x + h4.y * ww.y + h4.z * ww.z + h4.w * ww.w;
            }
            int p = tid & 127;
            if (which != 0) {
                smx[((which - 1) * 3 + 0) * 132 + p] = ar;
                smx[((which - 1) * 3 + 1) * 132 + p] = az;
                smx[((which - 1) * 3 + 2) * 132 + p] = an;
            }
            __syncthreads();
            if (which == 0) {
                float ar2 = ar + smx[0 * 132 + p];
                float az2 = az + smx[1 * 132 + p];
                float an2 = an + smx[2 * 132 + p];
                float cr = smx[3 * 132 + p] + smx[6 * 132 + p];
                float cz = smx[4 * 132 + p] + smx[7 * 132 + p];
                float cn = smx[5 * 132 + p] + smx[8 * 132 + p];
                const float* gi = g_gidec + ((size_t)t * BB + gb) * (3 * HD);
                float ghr = ar2 + db_r, ghz = az2 + db_z, ghn = an2 + db_n;
                float r = 1.f / (1.f + expf(-(__ldg(&gi[gu]) + cr + ghr)));
                float z = 1.f / (1.f + expf(-(__ldg(&gi[HD + gu]) + cz + ghz)));
                float n = tanhf(__ldg(&gi[2 * HD + gu]) + cn + r * ghn);
                float hp = shh[gb * 516 + gu];
                float hn2 = (1.f - z) * n + z * hp;
                g_hdec[(t + 1) & 1][gb * HD + gu] = hn2;
                g_decout[((size_t)gb * TT + t) * HD + gu] = hn2;
            }
        }
        bar_sync(cnt, (unsigned)(128 * (3 * t + 3)));
    }
}

// ---------------- host ----------------
extern "C" void kernel_launch(void* const* d_in, const int* in_sizes, int n_in,
                              void* d_out, int out_size) {
    const int*   src_ids = (const int*)d_in[0];
    const int*   trg_ids = (const int*)d_in[1];
    const float* src_emb = (const float*)d_in[2];
    const float* trg_emb = (const float*)d_in[3];
    const float* eWihf   = (const float*)d_in[4];
    const float* eWhhf   = (const float*)d_in[5];
    const float* ebihf   = (const float*)d_in[6];
    const float* ebhhf   = (const float*)d_in[7];
    const float* eWihb   = (const float*)d_in[8];
    const float* eWhhb   = (const float*)d_in[9];
    const float* ebihb   = (const float*)d_in[10];
    const float* ebhhb   = (const float*)d_in[11];
    const float* e2dW    = (const float*)d_in[12];
    const float* e2db    = (const float*)d_in[13];
    const float* dWih    = (const float*)d_in[14];
    const float* dWhh    = (const float*)d_in[15];
    const float* dbih    = (const float*)d_in[16];
    const float* dbhh    = (const float*)d_in[17];
    const float* outW    = (const float*)d_in[18];
    const float* outb    = (const float*)d_in[19];
    float* out = (float*)d_out;

    const int ENC_SMEM = (6144 + 32 * 260) * (int)sizeof(float);                    // 57856
    const int DEC_SMEM = (12288 + 2 * 16512 + 9 * 132) * (int)sizeof(float);        // 186000
    cudaFuncSetAttribute(enc_persist, cudaFuncAttributeMaxDynamicSharedMemorySize, ENC_SMEM);
    cudaFuncSetAttribute(dec_persist, cudaFuncAttributeMaxDynamicSharedMemorySize, DEC_SMEM);

    float *p_srcx, *p_trgx, *p_gif, *p_gib, *p_gidec, *p_hcat, *p_hdec, *p_decout;
    cudaGetSymbolAddress((void**)&p_srcx, g_srcx);
    cudaGetSymbolAddress((void**)&p_trgx, g_trgx);
    cudaGetSymbolAddress((void**)&p_gif, g_gif);
    cudaGetSymbolAddress((void**)&p_gib, g_gib);
    cudaGetSymbolAddress((void**)&p_gidec, g_gidec);
    cudaGetSymbolAddress((void**)&p_hcat, g_hcat);
    cudaGetSymbolAddress((void**)&p_hdec, g_hdec);
    cudaGetSymbolAddress((void**)&p_decout, g_decout);

    // 1) embeddings + prep
    embed_kernel<<<(SS * BB * (EE / 4) + 255) / 256, 256>>>(src_ids, src_emb, p_srcx, SS);
    embed_kernel<<<(TT * BB * (EE / 4) + 255) / 256, 256>>>(trg_ids, trg_emb, p_trgx, TT);
    prep_kernel<<<(2 * BB * HE + 255) / 256, 256>>>();

    // 2) time-parallel input-side GRU GEMMs (tf32)
    gemm_tf32<<<dim3(768 / 64, SS * BB / 128), 256>>>(p_srcx, eWihf, ebihf, p_gif, SS * BB, 768, 256, 256);
    gemm_tf32<<<dim3(768 / 64, SS * BB / 128), 256>>>(p_srcx, eWihb, ebihb, p_gib, SS * BB, 768, 256, 256);
    gemm_tf32<<<dim3(1536 / 64, TT * BB / 128), 256>>>(p_trgx, dWih, dbih, p_gidec, TT * BB, 1536, 256, 768);

    // 3) persistent encoder scan
    enc_persist<<<64, 256, ENC_SMEM>>>(eWhhf, eWhhb, ebhhf, ebhhb);

    // 4) h0 = tanh([hT_f,hT_b] @ e2d_W.T + e2d_b)
    hcat_kernel<<<(BB * 2 * HE + 255) / 256, 256>>>();
    gemm_atb<<<dim3(512 / 64, 1), 256>>>(p_hcat, e2dW, e2db, p_hdec, BB, 512, 512, 512, 1);

    // 5) persistent decoder scan
    dec_persist<<<128, 512, DEC_SMEM>>>(dWih, dWhh, dbhh);

    // 6) logits = dec_out @ out_W.T + out_b (tf32)
    gemm_tf32<<<dim3(VV / 64, BB * TT / 128), 256>>>(p_decout, outW, outb, out, BB * TT, VV, 512, 512);
}

// round 7
// speedup vs baseline: 3.0424x; 1.1577x over previous
#include <cuda_runtime.h>
#include <math.h>

#define BB 32
#define SS 400
#define TT 100
#define EE 256
#define HE 256
#define HD 512
#define VV 32000

// ---------------- scratch (device globals; no allocations) ----------------
__device__ float g_srcx[SS * BB * EE];
__device__ float g_trgx[TT * BB * EE];
__device__ float g_gif[SS * BB * 3 * HE];
__device__ float g_gib[SS * BB * 3 * HE];
__device__ float g_gidec[TT * BB * 3 * HD];
__device__ float g_enhy[BB * SS * 2 * HE];
__device__ float g_hT[2][2][HE * BB];     // [dir][parity][u*BB + b] (transposed)
__device__ float g_hcat[BB * 2 * HE];
__device__ float g_hdec[2][BB * HD];
__device__ float g_ctx[BB * HD];
__device__ float g_decout[BB * TT * HD];
__device__ float g_attm[4][BB];
__device__ float g_attl[4][BB];
__device__ float g_attc[4][BB][HD];
__device__ unsigned g_bar_cnt[4];         // monotonic counters: 0=enc dir0, 1=enc dir1, 2=dec

// ---------------- cheap monotonic grid barrier (tid0-only polling) ----------------
// All threads sync; tid0 release-arrives and acquire-polls the counter with
// backoff (one poller per CTA -> no same-address L2 storm); trailing sync.
__device__ __forceinline__ void bar_sync(unsigned* cnt, unsigned target) {
    __syncthreads();
    if (threadIdx.x == 0) {
        unsigned p;
        asm volatile("atom.release.gpu.global.add.u32 %0,[%1],%2;"
                     : "=r"(p) : "l"(cnt), "r"(1u) : "memory");
        if (p + 1u < target) {
            unsigned v;
            for (;;) {
                asm volatile("ld.acquire.gpu.global.u32 %0,[%1];" : "=r"(v) : "l"(cnt) : "memory");
                if (v >= target) break;
                __nanosleep(32);
            }
        }
    }
    __syncthreads();
}

// ---------------- embedding gather ----------------
__global__ void embed_kernel(const int* __restrict__ ids, const float* __restrict__ table,
                             float* __restrict__ out, int seq) {
    int i = blockIdx.x * blockDim.x + threadIdx.x;
    int E4 = EE / 4;
    int total = seq * BB * E4;
    if (i >= total) return;
    int e4 = i % E4;
    int sb = i / E4;
    int b = sb % BB;
    int s = sb / BB;
    int id = ids[b * seq + s];
    ((float4*)out)[i] = ((const float4*)table)[(size_t)id * E4 + e4];
}

// ---------------- prep ----------------
__global__ void prep_kernel() {
    int i = blockIdx.x * blockDim.x + threadIdx.x;
    if (i < 4) g_bar_cnt[i] = 0u;
    if (i < 2 * BB * HE) g_hT[i / (BB * HE)][0][i % (BB * HE)] = 0.f;
}

// ---------------- tf32 -> bits ----------------
__device__ __forceinline__ unsigned f2t(float x) {
    unsigned r; asm("cvt.rna.tf32.f32 %0, %1;" : "=r"(r) : "f"(x)); return r;
}

// ---------------- tf32 tensor-core GEMM v4: K templated, fully unrolled ----------------
// C = A(M,K)*B(N,K)^T + bias. 128x64 tile, 256 thr (8 warps, warp tile 32x32).
// 3-stage pipeline, prefetch distance 2; stage index is compile-time constant.
template<int KK>
__global__ void __launch_bounds__(256) gemm_tf32(
    const float* __restrict__ A, const float* __restrict__ Bm,
    const float* __restrict__ bias, float* __restrict__ C,
    int M, int N, int ldb)
{
    constexpr int NT = KK / 16;
    __shared__ unsigned sA[3][16][136];
    __shared__ unsigned sB[3][16][72];
    int bm = blockIdx.y * 128, bn = blockIdx.x * 64;
    int tid = threadIdx.x;
    int w = tid >> 5, lane = tid & 31;
    int wm = w & 3, wn = w >> 2;
    int g = lane >> 2, tg = lane & 3;
    int arow = tid >> 1, acol = (tid & 1) * 8;
    int brow = tid >> 2, bcol = (tid & 3) * 4;
    const float* Ap = A + (size_t)(bm + arow) * KK + acol;
    const float* Bp = Bm + (size_t)(bn + brow) * ldb + bcol;

    // tile 0 -> stage 0
    {
        float4 a0 = *(const float4*)Ap;
        float4 a1 = *(const float4*)(Ap + 4);
        float4 b0 = *(const float4*)Bp;
        sA[0][acol + 0][arow] = f2t(a0.x); sA[0][acol + 1][arow] = f2t(a0.y);
        sA[0][acol + 2][arow] = f2t(a0.z); sA[0][acol + 3][arow] = f2t(a0.w);
        sA[0][acol + 4][arow] = f2t(a1.x); sA[0][acol + 5][arow] = f2t(a1.y);
        sA[0][acol + 6][arow] = f2t(a1.z); sA[0][acol + 7][arow] = f2t(a1.w);
        sB[0][bcol + 0][brow] = f2t(b0.x); sB[0][bcol + 1][brow] = f2t(b0.y);
        sB[0][bcol + 2][brow] = f2t(b0.z); sB[0][bcol + 3][brow] = f2t(b0.w);
    }
    // tile 1 -> regs
    float4 pa0, pa1, pb;
    if (NT > 1) {
        pa0 = *(const float4*)(Ap + 16);
        pa1 = *(const float4*)(Ap + 20);
        pb  = *(const float4*)(Bp + 16);
    }
    __syncthreads();

    float d[2][4][4];
#pragma unroll
    for (int f = 0; f < 2; f++)
#pragma unroll
        for (int j = 0; j < 4; j++)
#pragma unroll
            for (int e = 0; e < 4; e++) d[f][j][e] = 0.f;

    int mr0 = wm * 32 + g;
    int nc0 = wn * 32 + g;

#pragma unroll
    for (int i = 0; i < NT; i++) {
        const int st = i % 3;                 // compile-time after unroll
        // ---- fragments for tile i from stage st ----
        unsigned a[2][2][4], bf[2][4][2];
#pragma unroll
        for (int kh = 0; kh < 2; kh++) {
            int kk = kh * 8;
#pragma unroll
            for (int f = 0; f < 2; f++) {
                int mr = mr0 + f * 16;
                a[kh][f][0] = sA[st][kk + tg][mr];
                a[kh][f][1] = sA[st][kk + tg][mr + 8];
                a[kh][f][2] = sA[st][kk + tg + 4][mr];
                a[kh][f][3] = sA[st][kk + tg + 4][mr + 8];
            }
#pragma unroll
            for (int j = 0; j < 4; j++) {
                int nc = nc0 + j * 8;
                bf[kh][j][0] = sB[st][kk + tg][nc];
                bf[kh][j][1] = sB[st][kk + tg + 4][nc];
            }
        }
        // ---- STS tile i+1 (regs loaded at i-1 / preloaded) ----
        if (i + 1 < NT) {
            const int ns = (i + 1) % 3;
            sA[ns][acol + 0][arow] = f2t(pa0.x); sA[ns][acol + 1][arow] = f2t(pa0.y);
            sA[ns][acol + 2][arow] = f2t(pa0.z); sA[ns][acol + 3][arow] = f2t(pa0.w);
            sA[ns][acol + 4][arow] = f2t(pa1.x); sA[ns][acol + 5][arow] = f2t(pa1.y);
            sA[ns][acol + 6][arow] = f2t(pa1.z); sA[ns][acol + 7][arow] = f2t(pa1.w);
            sB[ns][bcol + 0][brow] = f2t(pb.x);  sB[ns][bcol + 1][brow] = f2t(pb.y);
            sB[ns][bcol + 2][brow] = f2t(pb.z);  sB[ns][bcol + 3][brow] = f2t(pb.w);
        }
        // ---- LDG tile i+2 ----
        if (i + 2 < NT) {
            const int k = (i + 2) * 16;
            pa0 = *(const float4*)(Ap + k);
            pa1 = *(const float4*)(Ap + k + 4);
            pb  = *(const float4*)(Bp + k);
        }
        // ---- 16 MMAs ----
#pragma unroll
        for (int kh = 0; kh < 2; kh++)
#pragma unroll
            for (int f = 0; f < 2; f++)
#pragma unroll
                for (int j = 0; j < 4; j++)
                    asm volatile(
                        "mma.sync.aligned.m16n8k8.row.col.f32.tf32.tf32.f32 "
                        "{%0,%1,%2,%3}, {%4,%5,%6,%7}, {%8,%9}, {%0,%1,%2,%3};"
                        : "+f"(d[f][j][0]), "+f"(d[f][j][1]),
                          "+f"(d[f][j][2]), "+f"(d[f][j][3])
                        : "r"(a[kh][f][0]), "r"(a[kh][f][1]), "r"(a[kh][f][2]), "r"(a[kh][f][3]),
                          "r"(bf[kh][j][0]), "r"(bf[kh][j][1]));
        __syncthreads();
    }
#pragma unroll
    for (int f = 0; f < 2; f++) {
        int r0 = bm + wm * 32 + f * 16 + g;
#pragma unroll
        for (int j = 0; j < 4; j++) {
            int col = bn + wn * 32 + j * 8 + tg * 2;
            float b0 = __ldg(&bias[col]), b1 = __ldg(&bias[col + 1]);
            float2 v0 = make_float2(d[f][j][0] + b0, d[f][j][1] + b1);
            float2 v1 = make_float2(d[f][j][2] + b0, d[f][j][3] + b1);
            *(float2*)&C[(size_t)r0 * N + col] = v0;
            *(float2*)&C[(size_t)(r0 + 8) * N + col] = v1;
        }
    }
}

// ---------------- small fp32 GEMM (e2d only, M=32, tanh) ----------------
__global__ void __launch_bounds__(256) gemm_atb(
    const float* __restrict__ A, const float* __restrict__ Bm,
    const float* __restrict__ bias, float* __restrict__ C,
    int M, int N, int K, int ldb, int act)
{
    __shared__ float sA[16][68];
    __shared__ float sB[16][68];
    int bm = blockIdx.y * 64, bn = blockIdx.x * 64;
    int tid = threadIdx.x;
    int tm = (tid >> 4) << 2, tn = (tid & 15) << 2;
    int lr = tid >> 2, lc = (tid & 3) << 2;
    float acc[4][4] = {};
    for (int k0 = 0; k0 < K; k0 += 16) {
        float4 a4 = make_float4(0.f, 0.f, 0.f, 0.f);
        if (bm + lr < M) a4 = *(const float4*)&A[(size_t)(bm + lr) * K + k0 + lc];
        sA[lc + 0][lr] = a4.x; sA[lc + 1][lr] = a4.y; sA[lc + 2][lr] = a4.z; sA[lc + 3][lr] = a4.w;
        float4 b4 = *(const float4*)&Bm[(size_t)(bn + lr) * ldb + k0 + lc];
        sB[lc + 0][lr] = b4.x; sB[lc + 1][lr] = b4.y; sB[lc + 2][lr] = b4.z; sB[lc + 3][lr] = b4.w;
        __syncthreads();
#pragma unroll
        for (int kk = 0; kk < 16; kk++) {
            float4 av = *(const float4*)&sA[kk][tm];
            float4 bv = *(const float4*)&sB[kk][tn];
            float a[4] = {av.x, av.y, av.z, av.w};
            float b[4] = {bv.x, bv.y, bv.z, bv.w};
#pragma unroll
            for (int i = 0; i < 4; i++)
#pragma unroll
                for (int j = 0; j < 4; j++) acc[i][j] += a[i] * b[j];
        }
        __syncthreads();
    }
#pragma unroll
    for (int i = 0; i < 4; i++) {
        int row = bm + tm + i;
        if (row >= M) continue;
        float4 v;
        float* pv = &v.x;
#pragma unroll
        for (int j = 0; j < 4; j++) {
            float x = acc[i][j] + bias[bn + tn + j];
            if (act == 1) x = tanhf(x);
            pv[j] = x;
        }
        *(float4*)&C[(size_t)row * N + bn + tn] = v;
    }
}

// ---------------- persistent encoder: 64 CTAs x 256 thr ----------------
__global__ void __launch_bounds__(256) enc_persist(
    const float* __restrict__ Whh_f, const float* __restrict__ Whh_b,
    const float* __restrict__ bhh_f, const float* __restrict__ bhh_b)
{
    extern __shared__ float es[];
    float* swt = es;            // [3*8*256]
    float* sh  = es + 6144;     // [32][260]
    int c = blockIdx.x;
    int dir = c >> 5;
    int ublk = c & 31;
    int tid = threadIdx.x;
    int b = tid & 31;
    int ul = tid >> 5;
    int u = ublk * 8 + ul;
    const float* Whh = dir ? Whh_b : Whh_f;
    const float* bhh = dir ? bhh_b : bhh_f;
    const float* gibase = dir ? g_gib : g_gif;
    for (int i = tid; i < 6144; i += 256) {
        int gate = i >> 11;
        int rem = i & 2047;
        swt[i] = Whh[((size_t)gate * HE + ublk * 8 + (rem >> 8)) * HE + (rem & 255)];
    }
    float br_ = bhh[u], bz_ = bhh[HE + u], bn_ = bhh[2 * HE + u];
    const float4* wr = (const float4*)&swt[(0 * 8 + ul) * 256];
    const float4* wz = (const float4*)&swt[(1 * 8 + ul) * 256];
    const float4* wn = (const float4*)&swt[(2 * 8 + ul) * 256];
    unsigned* cnt = &g_bar_cnt[dir];
    const float* hb = sh + b * 260;

    for (int t = 0; t < SS; t++) {
        if (t > 0) bar_sync(cnt, (unsigned)(32 * t));
        const float* hsrc = g_hT[dir][t & 1];
        for (int i = tid; i < BB * HE; i += 256)
            sh[(i & 31) * 260 + (i >> 5)] = __ldcg(&hsrc[i]);
        __syncthreads();
        float ar = 0.f, az = 0.f, an = 0.f;
#pragma unroll 8
        for (int k4 = 0; k4 < 64; k4++) {
            float4 h4 = *(const float4*)(hb + k4 * 4);
            float4 ww;
            ww = wr[k4]; ar += h4.x * ww.x + h4.y * ww.y + h4.z * ww.z + h4.w * ww.w;
            ww = wz[k4]; az += h4.x * ww.x + h4.y * ww.y + h4.z * ww.z + h4.w * ww.w;
            ww = wn[k4]; an += h4.x * ww.x + h4.y * ww.y + h4.z * ww.z + h4.w * ww.w;
        }
        int s = dir ? (SS - 1 - t) : t;
        const float* gi = gibase + (size_t)(s * BB + b) * (3 * HE);
        float ghr = ar + br_, ghz = az + bz_, ghn = an + bn_;
        float r = 1.f / (1.f + expf(-(__ldg(&gi[u]) + ghr)));
        float z = 1.f / (1.f + expf(-(__ldg(&gi[HE + u]) + ghz)));
        float n = tanhf(__ldg(&gi[2 * HE + u]) + r * ghn);
        float hp = hb[u];
        float hn2 = (1.f - z) * n + z * hp;
        g_hT[dir][(t + 1) & 1][u * BB + b] = hn2;
        g_enhy[((size_t)b * SS + s) * (2 * HE) + dir * HE + u] = hn2;
        __syncthreads();
    }
}

// ---------------- build [hT_f, hT_b] ----------------
__global__ void hcat_kernel() {
    int i = blockIdx.x * blockDim.x + threadIdx.x;
    if (i >= BB * 2 * HE) return;
    int b = i >> 9;
    int j = i & 511;
    float v;
    if (j < HE) v = g_enhy[((size_t)b * SS + (SS - 1)) * (2 * HE) + j];
    else        v = g_enhy[((size_t)b * SS + 0) * (2 * HE) + j];
    g_hcat[i] = v;
}

// ---------------- persistent decoder: 128 CTAs x 512 thr ----------------
__global__ void __launch_bounds__(512) dec_persist(
    const float* __restrict__ dWih, const float* __restrict__ dWhh,
    const float* __restrict__ dbhh)
{
    extern __shared__ float sm[];
    float* swd = sm;                    // [12288]
    float* shh = sm + 12288;            // [32][516]
    float* shc = shh + 16512;           // [32][516]
    float* smx = shc + 16512;           // [9*132]
    float* sm_m   = sm + 12288;
    float* sm_l   = sm_m + 16;
    float* sm_ctx = sm_l + 16;

    int c = blockIdx.x;
    int tid = threadIdx.x;
    int lane = tid & 31, w = tid >> 5;
    int ab = c & 31, chunk = c >> 5, s0 = chunk * (SS / 4);
    int gb = tid & 31;
    int slot = (tid >> 5) & 3;
    int which = tid >> 7;
    int gu = c * 4 + slot;

    for (int i = tid; i < 12288; i += 512) {
        int sg = i >> 11;
        int rem = i & 2047;
        int sl = rem >> 9;
        int k = rem & 511;
        int s_ = sg / 3, g2 = sg % 3;
        int uu = c * 4 + sl;
        swd[i] = (s_ == 0) ? dWhh[((size_t)g2 * HD + uu) * HD + k]
                           : dWih[((size_t)(g2 * HD + uu)) * 768 + 256 + k];
    }
    int ws = which >> 1;
    int kb = (which & 1) * 256;
    const float4* vr = (const float4*)&swd[((ws * 3 + 0) * 4 + slot) * 512 + kb];
    const float4* vz = (const float4*)&swd[((ws * 3 + 1) * 4 + slot) * 512 + kb];
    const float4* vn = (const float4*)&swd[((ws * 3 + 2) * 4 + slot) * 512 + kb];
    float db_r = dbhh[gu], db_z = dbhh[HD + gu], db_n = dbhh[2 * HD + gu];
    unsigned* cnt = &g_bar_cnt[2];
    __syncthreads();

    for (int t = 0; t < TT; t++) {
        const float* hcur = g_hdec[t & 1];
        // ---------- Phase A: flash attention partials ----------
        {
            const float* hd = hcur + ab * HD;
            float4 hreg[4];
#pragma unroll
            for (int j = 0; j < 4; j++)
                hreg[j] = __ldcg((const float4*)(hd + (j * 32 + lane) * 4));
            const float* eb = g_enhy + (size_t)ab * SS * HD;
            float m = -1e30f, l = 0.f;
            float4 cacc[4];
#pragma unroll
            for (int j = 0; j < 4; j++) cacc[j] = make_float4(0.f, 0.f, 0.f, 0.f);
            for (int s = s0 + w; s < s0 + SS / 4; s += 16) {
                const float4* e4 = (const float4*)(eb + (size_t)s * HD);
                float4 ev[4];
                float acc = 0.f;
#pragma unroll
                for (int j = 0; j < 4; j++) {
                    ev[j] = __ldg(&e4[j * 32 + lane]);
                    acc += ev[j].x * hreg[j].x + ev[j].y * hreg[j].y
                         + ev[j].z * hreg[j].z + ev[j].w * hreg[j].w;
                }
#pragma unroll
                for (int o = 16; o; o >>= 1) acc += __shfl_xor_sync(0xffffffffu, acc, o);
                float mnew = fmaxf(m, acc);
                float scale = __expf(m - mnew);
                float p = __expf(acc - mnew);
                l = l * scale + p;
#pragma unroll
                for (int j = 0; j < 4; j++) {
                    cacc[j].x = cacc[j].x * scale + p * ev[j].x;
                    cacc[j].y = cacc[j].y * scale + p * ev[j].y;
                    cacc[j].z = cacc[j].z * scale + p * ev[j].z;
                    cacc[j].w = cacc[j].w * scale + p * ev[j].w;
                }
                m = mnew;
            }
            if (lane == 0) { sm_m[w] = m; sm_l[w] = l; }
#pragma unroll
            for (int j = 0; j < 4; j++)
                ((float4*)(sm_ctx + w * HD))[j * 32 + lane] = cacc[j];
            __syncthreads();
            float M = -1e30f;
#pragma unroll
            for (int q = 0; q < 16; q++) M = fmaxf(M, sm_m[q]);
            float L = 0.f, vv = 0.f;
            int e = tid;
#pragma unroll
            for (int q = 0; q < 16; q++) {
                float f_ = __expf(sm_m[q] - M);
                L += sm_l[q] * f_;
                vv += sm_ctx[q * HD + e] * f_;
            }
            g_attc[chunk][ab][e] = vv;
            if (tid == 0) { g_attm[chunk][ab] = M; g_attl[chunk][ab] = L; }
        }
        bar_sync(cnt, (unsigned)(128 * (3 * t + 1)));
        // ---------- Phase R: distributed combine ----------
        if (tid < 128) {
            int idx = c * 128 + tid;
            int b2 = idx >> 9, e = idx & 511;
            float m0 = __ldcg(&g_attm[0][b2]), m1 = __ldcg(&g_attm[1][b2]);
            float m2 = __ldcg(&g_attm[2][b2]), m3 = __ldcg(&g_attm[3][b2]);
            float M = fmaxf(fmaxf(m0, m1), fmaxf(m2, m3));
            float f0 = __expf(m0 - M), f1 = __expf(m1 - M);
            float f2 = __expf(m2 - M), f3 = __expf(m3 - M);
            float L = __ldcg(&g_attl[0][b2]) * f0 + __ldcg(&g_attl[1][b2]) * f1
                    + __ldcg(&g_attl[2][b2]) * f2 + __ldcg(&g_attl[3][b2]) * f3;
            float v = __ldcg(&g_attc[0][b2][e]) * f0 + __ldcg(&g_attc[1][b2][e]) * f1
                    + __ldcg(&g_attc[2][b2][e]) * f2 + __ldcg(&g_attc[3][b2][e]) * f3;
            g_ctx[b2 * HD + e] = tanhf(v / L);
        }
        bar_sync(cnt, (unsigned)(128 * (3 * t + 2)));
        // ---------- Phase G: GRU step ----------
        {
            for (int i4 = tid; i4 < BB * HD / 4; i4 += 512) {
                int b2 = i4 >> 7, k = (i4 & 127) * 4;
                *(float4*)&shh[b2 * 516 + k] = __ldcg((const float4*)&hcur[i4 * 4]);
                *(float4*)&shc[b2 * 516 + k] = __ldcg((const float4*)&g_ctx[i4 * 4]);
            }
            __syncthreads();
            const float* src = (ws ? shc : shh) + gb * 516 + kb;
            float ar = 0.f, az = 0.f, an = 0.f;
#pragma unroll 8
            for (int k4 = 0; k4 < 64; k4++) {
                float4 h4 = *(const float4*)(src + k4 * 4);
                float4 ww;
                ww = vr[k4]; ar += h4.x * ww.x + h4.y * ww.y + h4.z * ww.z + h4.w * ww.w;
                ww = vz[k4]; az += h4.x * ww.x + h4.y * ww.y + h4.z * ww.z + h4.w * ww.w;
                ww = vn[k4]; an += h4.x * ww.x + h4.y * ww.y + h4.z * ww.z + h4.w * ww.w;
            }
            int p = tid & 127;
            if (which != 0) {
                smx[((which - 1) * 3 + 0) * 132 + p] = ar;
                smx[((which - 1) * 3 + 1) * 132 + p] = az;
                smx[((which - 1) * 3 + 2) * 132 + p] = an;
            }
            __syncthreads();
            if (which == 0) {
                float ar2 = ar + smx[0 * 132 + p];
                float az2 = az + smx[1 * 132 + p];
                float an2 = an + smx[2 * 132 + p];
                float cr = smx[3 * 132 + p] + smx[6 * 132 + p];
                float cz = smx[4 * 132 + p] + smx[7 * 132 + p];
                float cn = smx[5 * 132 + p] + smx[8 * 132 + p];
                const float* gi = g_gidec + ((size_t)t * BB + gb) * (3 * HD);
                float ghr = ar2 + db_r, ghz = az2 + db_z, ghn = an2 + db_n;
                float r = 1.f / (1.f + expf(-(__ldg(&gi[gu]) + cr + ghr)));
                float z = 1.f / (1.f + expf(-(__ldg(&gi[HD + gu]) + cz + ghz)));
                float n = tanhf(__ldg(&gi[2 * HD + gu]) + cn + r * ghn);
                float hp = shh[gb * 516 + gu];
                float hn2 = (1.f - z) * n + z * hp;
                g_hdec[(t + 1) & 1][gb * HD + gu] = hn2;
                g_decout[((size_t)gb * TT + t) * HD + gu] = hn2;
            }
        }
        bar_sync(cnt, (unsigned)(128 * (3 * t + 3)));
    }
}

// ---------------- host ----------------
extern "C" void kernel_launch(void* const* d_in, const int* in_sizes, int n_in,
                              void* d_out, int out_size) {
    const int*   src_ids = (const int*)d_in[0];
    const int*   trg_ids = (const int*)d_in[1];
    const float* src_emb = (const float*)d_in[2];
    const float* trg_emb = (const float*)d_in[3];
    const float* eWihf   = (const float*)d_in[4];
    const float* eWhhf   = (const float*)d_in[5];
    const float* ebihf   = (const float*)d_in[6];
    const float* ebhhf   = (const float*)d_in[7];
    const float* eWihb   = (const float*)d_in[8];
    const float* eWhhb   = (const float*)d_in[9];
    const float* ebihb   = (const float*)d_in[10];
    const float* ebhhb   = (const float*)d_in[11];
    const float* e2dW    = (const float*)d_in[12];
    const float* e2db    = (const float*)d_in[13];
    const float* dWih    = (const float*)d_in[14];
    const float* dWhh    = (const float*)d_in[15];
    const float* dbih    = (const float*)d_in[16];
    const float* dbhh    = (const float*)d_in[17];
    const float* outW    = (const float*)d_in[18];
    const float* outb    = (const float*)d_in[19];
    float* out = (float*)d_out;

    const int ENC_SMEM = (6144 + 32 * 260) * (int)sizeof(float);
    const int DEC_SMEM = (12288 + 2 * 16512 + 9 * 132) * (int)sizeof(float);
    cudaFuncSetAttribute(enc_persist, cudaFuncAttributeMaxDynamicSharedMemorySize, ENC_SMEM);
    cudaFuncSetAttribute(dec_persist, cudaFuncAttributeMaxDynamicSharedMemorySize, DEC_SMEM);

    float *p_srcx, *p_trgx, *p_gif, *p_gib, *p_gidec, *p_hcat, *p_hdec, *p_decout;
    cudaGetSymbolAddress((void**)&p_srcx, g_srcx);
    cudaGetSymbolAddress((void**)&p_trgx, g_trgx);
    cudaGetSymbolAddress((void**)&p_gif, g_gif);
    cudaGetSymbolAddress((void**)&p_gib, g_gib);
    cudaGetSymbolAddress((void**)&p_gidec, g_gidec);
    cudaGetSymbolAddress((void**)&p_hcat, g_hcat);
    cudaGetSymbolAddress((void**)&p_hdec, g_hdec);
    cudaGetSymbolAddress((void**)&p_decout, g_decout);

    // 1) embeddings + prep
    embed_kernel<<<(SS * BB * (EE / 4) + 255) / 256, 256>>>(src_ids, src_emb, p_srcx, SS);
    embed_kernel<<<(TT * BB * (EE / 4) + 255) / 256, 256>>>(trg_ids, trg_emb, p_trgx, TT);
    prep_kernel<<<(2 * BB * HE + 255) / 256, 256>>>();

    // 2) time-parallel input-side GRU GEMMs (tf32, K=256)
    gemm_tf32<256><<<dim3(768 / 64, SS * BB / 128), 256>>>(p_srcx, eWihf, ebihf, p_gif, SS * BB, 768, 256);
    gemm_tf32<256><<<dim3(768 / 64, SS * BB / 128), 256>>>(p_srcx, eWihb, ebihb, p_gib, SS * BB, 768, 256);
    gemm_tf32<256><<<dim3(1536 / 64, TT * BB / 128), 256>>>(p_trgx, dWih, dbih, p_gidec, TT * BB, 1536, 768);

    // 3) persistent encoder scan
    enc_persist<<<64, 256, ENC_SMEM>>>(eWhhf, eWhhb, ebhhf, ebhhb);

    // 4) h0 = tanh([hT_f,hT_b] @ e2d_W.T + e2d_b)
    hcat_kernel<<<(BB * 2 * HE + 255) / 256, 256>>>();
    gemm_atb<<<dim3(512 / 64, 1), 256>>>(p_hcat, e2dW, e2db, p_hdec, BB, 512, 512, 512, 1);

    // 5) persistent decoder scan
    dec_persist<<<128, 512, DEC_SMEM>>>(dWih, dWhh, dbhh);

    // 6) logits = dec_out @ out_W.T + out_b (tf32, K=512)
    gemm_tf32<512><<<dim3(VV / 64, BB * TT / 128), 256>>>(p_decout, outW, outb, out, BB * TT, VV, 512);
}